// round 1
// baseline (speedup 1.0000x reference)
#include <cuda_runtime.h>
#include <math.h>

#define HID 768
#define HEADS 12
#define DH 64
#define WW 256
#define NC 16
#define FFNDIM 3072
#define NLAB 8921
#define BB 2
#define SS 4096
#define NTOK (BB*SS)

// -------- scratch (device globals; no allocation allowed) --------
__device__ float g_x[NTOK*HID];
__device__ float g_q[NTOK*HID];
__device__ float g_k[NTOK*HID];
__device__ float g_v[NTOK*HID];
__device__ float g_kg[NTOK*HID];
__device__ float g_vg[NTOK*HID];
__device__ float g_attn[NTOK*HID];
__device__ float g_tmp[NTOK*HID];
__device__ float g_ffn[NTOK*FFNDIM];
__device__ float g_qg0[BB*HID];

// -------- block reduction helpers (256 threads) --------
__device__ __forceinline__ float blk_sum256(float v, float* red) {
    #pragma unroll
    for (int o = 16; o > 0; o >>= 1) v += __shfl_xor_sync(0xffffffffu, v, o);
    int w = threadIdx.x >> 5, ln = threadIdx.x & 31;
    if (ln == 0) red[w] = v;
    __syncthreads();
    if (w == 0) {
        float t = (ln < 8) ? red[ln] : 0.0f;
        #pragma unroll
        for (int o = 4; o > 0; o >>= 1) t += __shfl_xor_sync(0xffffffffu, t, o);
        if (ln == 0) red[0] = t;
    }
    __syncthreads();
    float r = red[0];
    __syncthreads();
    return r;
}

__device__ __forceinline__ float blk_max256(float v, float* red) {
    #pragma unroll
    for (int o = 16; o > 0; o >>= 1) v = fmaxf(v, __shfl_xor_sync(0xffffffffu, v, o));
    int w = threadIdx.x >> 5, ln = threadIdx.x & 31;
    if (ln == 0) red[w] = v;
    __syncthreads();
    if (w == 0) {
        float t = (ln < 8) ? red[ln] : -3.0e38f;
        #pragma unroll
        for (int o = 4; o > 0; o >>= 1) t = fmaxf(t, __shfl_xor_sync(0xffffffffu, t, o));
        if (ln == 0) red[0] = t;
    }
    __syncthreads();
    float r = red[0];
    __syncthreads();
    return r;
}

// -------- embedding + LN --------
__global__ __launch_bounds__(256) void k_embed(
    const int* __restrict__ ids, const float* __restrict__ wemb,
    const float* __restrict__ pemb, const float* __restrict__ lns,
    const float* __restrict__ lnb, float* __restrict__ xout)
{
    __shared__ float red[32];
    int row = blockIdx.x;
    int tid = threadIdx.x;
    int s = row & (SS - 1);
    int id = ids[row];
    const float* we = wemb + (size_t)id * HID;
    const float* pe = pemb + (size_t)s * HID;
    float v0 = we[tid]       + pe[tid];
    float v1 = we[tid + 256] + pe[tid + 256];
    float v2 = we[tid + 512] + pe[tid + 512];
    float mean = blk_sum256(v0 + v1 + v2, red) * (1.0f / HID);
    v0 -= mean; v1 -= mean; v2 -= mean;
    float var = blk_sum256(v0*v0 + v1*v1 + v2*v2, red) * (1.0f / HID);
    float r = rsqrtf(var + 1e-5f);
    size_t base = (size_t)row * HID;
    xout[base + tid]       = v0 * r * lns[tid]       + lnb[tid];
    xout[base + tid + 256] = v1 * r * lns[tid + 256] + lnb[tid + 256];
    xout[base + tid + 512] = v2 * r * lns[tid + 512] + lnb[tid + 512];
}

// -------- residual add + LN (in-place on x) --------
__global__ __launch_bounds__(256) void k_addln(
    const float* __restrict__ add, const float* __restrict__ lns,
    const float* __restrict__ lnb, float* __restrict__ x)
{
    __shared__ float red[32];
    int row = blockIdx.x;
    int tid = threadIdx.x;
    size_t base = (size_t)row * HID;
    float v0 = x[base + tid]       + add[base + tid];
    float v1 = x[base + tid + 256] + add[base + tid + 256];
    float v2 = x[base + tid + 512] + add[base + tid + 512];
    float mean = blk_sum256(v0 + v1 + v2, red) * (1.0f / HID);
    v0 -= mean; v1 -= mean; v2 -= mean;
    float var = blk_sum256(v0*v0 + v1*v1 + v2*v2, red) * (1.0f / HID);
    float r = rsqrtf(var + 1e-5f);
    x[base + tid]       = v0 * r * lns[tid]       + lnb[tid];
    x[base + tid + 256] = v1 * r * lns[tid + 256] + lnb[tid + 256];
    x[base + tid + 512] = v2 * r * lns[tid + 512] + lnb[tid + 512];
}

// -------- tiled SGEMM: C[M,N] = A[M,K] @ W[K,N] + bias  (ACT=1 -> exact GELU) --------
template <int ACT>
__global__ __launch_bounds__(256) void k_sgemm(
    const float* __restrict__ A, const float* __restrict__ Bw,
    const float* __restrict__ bias, float* __restrict__ C,
    int M, int N, int K)
{
    const int BM = 128, BN = 128, BK = 8, TM = 8, TN = 8;
    __shared__ float As[BK][BM];
    __shared__ float Bs[BK][BN];
    int tid = threadIdx.x;
    const float* Ab = A + (size_t)blockIdx.y * BM * K;
    const float* Bb = Bw + (size_t)blockIdx.x * BN;
    float* Cb = C + (size_t)blockIdx.y * BM * N + (size_t)blockIdx.x * BN;
    const float* bb = bias + (size_t)blockIdx.x * BN;

    int aRow = tid >> 1;
    int aCol = (tid & 1) << 2;
    int bRow = tid >> 5;
    int bCol = (tid & 31) << 2;
    int tRow = (tid >> 4) << 3;
    int tCol = (tid & 15) << 3;

    float acc[TM][TN];
    #pragma unroll
    for (int i = 0; i < TM; i++)
        #pragma unroll
        for (int j = 0; j < TN; j++) acc[i][j] = 0.0f;

    for (int k0 = 0; k0 < K; k0 += BK) {
        float4 a4 = *reinterpret_cast<const float4*>(Ab + (size_t)aRow * K + k0 + aCol);
        As[aCol + 0][aRow] = a4.x;
        As[aCol + 1][aRow] = a4.y;
        As[aCol + 2][aRow] = a4.z;
        As[aCol + 3][aRow] = a4.w;
        *reinterpret_cast<float4*>(&Bs[bRow][bCol]) =
            *reinterpret_cast<const float4*>(Bb + (size_t)(k0 + bRow) * N + bCol);
        __syncthreads();
        #pragma unroll
        for (int kk = 0; kk < BK; kk++) {
            float regM[TM], regN[TN];
            #pragma unroll
            for (int i = 0; i < TM; i++) regM[i] = As[kk][tRow + i];
            #pragma unroll
            for (int j = 0; j < TN; j++) regN[j] = Bs[kk][tCol + j];
            #pragma unroll
            for (int i = 0; i < TM; i++)
                #pragma unroll
                for (int j = 0; j < TN; j++)
                    acc[i][j] = fmaf(regM[i], regN[j], acc[i][j]);
        }
        __syncthreads();
    }
    #pragma unroll
    for (int i = 0; i < TM; i++) {
        #pragma unroll
        for (int j = 0; j < TN; j++) {
            float cv = acc[i][j] + bb[tCol + j];
            if (ACT == 1) cv = 0.5f * cv * (1.0f + erff(cv * 0.70710678118654752440f));
            acc[i][j] = cv;
        }
        #pragma unroll
        for (int j = 0; j < TN; j += 4) {
            float4 o = make_float4(acc[i][j], acc[i][j+1], acc[i][j+2], acc[i][j+3]);
            *reinterpret_cast<float4*>(Cb + (size_t)(tRow + i) * N + tCol + j) = o;
        }
    }
}

// -------- qg projection for CLS token only: qg0[b,:] = x[b,0,:] @ Wqg + bqg --------
__global__ __launch_bounds__(256) void k_qg0(
    const float* __restrict__ x, const float* __restrict__ Wg,
    const float* __restrict__ bg, float* __restrict__ outq)
{
    int b = blockIdx.y;
    int n = blockIdx.x * 256 + threadIdx.x;
    __shared__ float xs[HID];
    for (int i = threadIdx.x; i < HID; i += 256) xs[i] = x[(size_t)b * SS * HID + i];
    __syncthreads();
    float acc = bg[n];
    for (int kk = 0; kk < HID; kk++) acc = fmaf(xs[kk], Wg[(size_t)kk * HID + n], acc);
    outq[b * HID + n] = acc;
}

// -------- banded sliding-window attention + global-key column (online softmax) --------
#define KT 32
__global__ __launch_bounds__(256) void k_band(
    const float* __restrict__ q, const float* __restrict__ k,
    const float* __restrict__ v, const float* __restrict__ kg,
    const float* __restrict__ vg, const int* __restrict__ am,
    float* __restrict__ out)
{
    int c = blockIdx.x, h = blockIdx.y, b = blockIdx.z;
    int p = threadIdx.x;               // one query per thread
    int tid = threadIdx.x;
    int qpos = c * WW + p;
    int cstart = (c - 1) * WW;

    __shared__ float4 ks[KT][16];
    __shared__ float4 vs[KT][16];
    __shared__ float kg0[DH], vg0[DH];
    __shared__ unsigned char kval[3 * WW];

    if (tid < DH) {
        kg0[tid] = kg[(size_t)(b * SS) * HID + h * DH + tid];
        vg0[tid] = vg[(size_t)(b * SS) * HID + h * DH + tid];
    }
    for (int j = tid; j < 3 * WW; j += 256) {
        int kp = cstart + j;
        kval[j] = (kp > 0 && kp < SS && am[b * SS + kp] > 0) ? 1 : 0;
    }
    float4 qv[16];
    {
        const float4* qp4 = reinterpret_cast<const float4*>(
            q + (size_t)(b * SS + qpos) * HID + h * DH);
        #pragma unroll
        for (int i = 0; i < 16; i++) qv[i] = qp4[i];
    }
    __syncthreads();

    // initialize online softmax with the global (CLS key) column
    float m;
    {
        float acc = 0.0f;
        #pragma unroll
        for (int i = 0; i < 16; i++) {
            float4 k4 = reinterpret_cast<const float4*>(kg0)[i];
            acc += qv[i].x * k4.x + qv[i].y * k4.y + qv[i].z * k4.z + qv[i].w * k4.w;
        }
        m = acc * 0.125f;
    }
    float l = 1.0f;
    float4 accv[16];
    #pragma unroll
    for (int i = 0; i < 16; i++) accv[i] = reinterpret_cast<const float4*>(vg0)[i];

    for (int kt0 = 0; kt0 < 3 * WW; kt0 += KT) {
        __syncthreads();
        for (int t = tid; t < KT * 16; t += 256) {
            int jj = t >> 4, dd = t & 15;
            int kp = cstart + kt0 + jj;
            float4 kv4 = make_float4(0, 0, 0, 0), vv4 = make_float4(0, 0, 0, 0);
            if (kp >= 0 && kp < SS) {
                size_t base = (size_t)(b * SS + kp) * HID + h * DH;
                kv4 = *reinterpret_cast<const float4*>(k + base + dd * 4);
                vv4 = *reinterpret_cast<const float4*>(v + base + dd * 4);
            }
            ks[jj][dd] = kv4;
            vs[jj][dd] = vv4;
        }
        __syncthreads();
        int jlo = max(p - kt0, 0);
        int jhi = min(p + 2 * WW - kt0, KT - 1);
        for (int jj = jlo; jj <= jhi; jj++) {
            int j = kt0 + jj;
            if (!kval[j]) continue;
            float acc = 0.0f;
            #pragma unroll
            for (int i = 0; i < 16; i++) {
                float4 k4 = ks[jj][i];
                acc += qv[i].x * k4.x + qv[i].y * k4.y + qv[i].z * k4.z + qv[i].w * k4.w;
            }
            float sscore = acc * 0.125f;
            float mnew = fmaxf(m, sscore);
            float fac = __expf(m - mnew);
            float wgt = __expf(sscore - mnew);
            l = l * fac + wgt;
            #pragma unroll
            for (int i = 0; i < 16; i++) {
                float4 vv4 = vs[jj][i];
                accv[i].x = accv[i].x * fac + wgt * vv4.x;
                accv[i].y = accv[i].y * fac + wgt * vv4.y;
                accv[i].z = accv[i].z * fac + wgt * vv4.z;
                accv[i].w = accv[i].w * fac + wgt * vv4.w;
            }
            m = mnew;
        }
    }
    float inv = 1.0f / l;
    float4* op4 = reinterpret_cast<float4*>(out + (size_t)(b * SS + qpos) * HID + h * DH);
    #pragma unroll
    for (int i = 0; i < 16; i++) {
        accv[i].x *= inv; accv[i].y *= inv; accv[i].z *= inv; accv[i].w *= inv;
        op4[i] = accv[i];
    }
}

// -------- global (CLS) query: full attention over all S tokens, overwrites row 0 --------
__global__ __launch_bounds__(256) void k_glob(
    const float* __restrict__ qg0, const float* __restrict__ kg,
    const float* __restrict__ vg, const int* __restrict__ am,
    float* __restrict__ out)
{
    int b = blockIdx.x / HEADS;
    int h = blockIdx.x % HEADS;
    int tid = threadIdx.x;
    __shared__ float sc[SS];
    __shared__ float q0[DH];
    __shared__ float red[32];
    __shared__ float part[4][DH];

    if (tid < DH) q0[tid] = qg0[b * HID + h * DH + tid];
    __syncthreads();

    float lmax = -3.0e38f;
    for (int j = tid; j < SS; j += 256) {
        float sv = -1e9f;
        if (am[b * SS + j] > 0) {
            const float4* kr = reinterpret_cast<const float4*>(
                kg + (size_t)(b * SS + j) * HID + h * DH);
            float acc = 0.0f;
            #pragma unroll
            for (int i = 0; i < 16; i++) {
                float4 k4 = kr[i];
                float4 q4 = reinterpret_cast<const float4*>(q0)[i];
                acc += q4.x * k4.x + q4.y * k4.y + q4.z * k4.z + q4.w * k4.w;
            }
            sv = acc * 0.125f;
        }
        sc[j] = sv;
        lmax = fmaxf(lmax, sv);
    }
    float mm = blk_max256(lmax, red);
    float ls = 0.0f;
    for (int j = tid; j < SS; j += 256) {
        float w = __expf(sc[j] - mm);
        sc[j] = w;
        ls += w;
    }
    float sum = blk_sum256(ls, red);
    __syncthreads();

    int d = tid & 63, g = tid >> 6;
    float acc = 0.0f;
    for (int j = g; j < SS; j += 4)
        acc = fmaf(sc[j], vg[(size_t)(b * SS + j) * HID + h * DH + d], acc);
    part[g][d] = acc;
    __syncthreads();
    if (tid < DH) {
        float o = (part[0][tid] + part[1][tid] + part[2][tid] + part[3][tid]) / sum;
        out[(size_t)(b * SS) * HID + h * DH + tid] = o;
    }
}

// -------- classifier head: out[b,:] = x[b,0,:] @ head_W + head_b --------
__global__ __launch_bounds__(128) void k_head(
    const float* __restrict__ x, const float* __restrict__ hw,
    const float* __restrict__ hb, float* __restrict__ out)
{
    int b = blockIdx.y;
    int n = blockIdx.x * 128 + threadIdx.x;
    __shared__ float xs[HID];
    for (int i = threadIdx.x; i < HID; i += 128) xs[i] = x[(size_t)b * SS * HID + i];
    __syncthreads();
    if (n >= NLAB) return;
    float acc = hb[n];
    for (int kk = 0; kk < HID; kk++) acc = fmaf(xs[kk], hw[(size_t)kk * NLAB + n], acc);
    out[b * NLAB + n] = acc;
}

// -------- orchestration --------
extern "C" void kernel_launch(void* const* d_in, const int* in_sizes, int n_in,
                              void* d_out, int out_size)
{
    const int*   ids  = (const int*)d_in[0];
    const int*   am   = (const int*)d_in[1];
    const float* wemb = (const float*)d_in[2];
    const float* pemb = (const float*)d_in[3];
    const float* elns = (const float*)d_in[4];
    const float* elnb = (const float*)d_in[5];
    const float* Wq   = (const float*)d_in[6];
    const float* bq   = (const float*)d_in[7];
    const float* Wk   = (const float*)d_in[8];
    const float* bk   = (const float*)d_in[9];
    const float* Wv   = (const float*)d_in[10];
    const float* bv   = (const float*)d_in[11];
    const float* Wqg  = (const float*)d_in[12];
    const float* bqg  = (const float*)d_in[13];
    const float* Wkg  = (const float*)d_in[14];
    const float* bkg  = (const float*)d_in[15];
    const float* Wvg  = (const float*)d_in[16];
    const float* bvg  = (const float*)d_in[17];
    const float* Wo   = (const float*)d_in[18];
    const float* bo   = (const float*)d_in[19];
    const float* ln1s = (const float*)d_in[20];
    const float* ln1b = (const float*)d_in[21];
    const float* W1   = (const float*)d_in[22];
    const float* b1   = (const float*)d_in[23];
    const float* W2   = (const float*)d_in[24];
    const float* b2   = (const float*)d_in[25];
    const float* ln2s = (const float*)d_in[26];
    const float* ln2b = (const float*)d_in[27];
    const float* hW   = (const float*)d_in[28];
    const float* hb   = (const float*)d_in[29];
    float* out = (float*)d_out;

    float *px, *pq, *pk, *pv, *pkg, *pvg, *pattn, *ptmp, *pffn, *pqg0;
    cudaGetSymbolAddress((void**)&px,   g_x);
    cudaGetSymbolAddress((void**)&pq,   g_q);
    cudaGetSymbolAddress((void**)&pk,   g_k);
    cudaGetSymbolAddress((void**)&pv,   g_v);
    cudaGetSymbolAddress((void**)&pkg,  g_kg);
    cudaGetSymbolAddress((void**)&pvg,  g_vg);
    cudaGetSymbolAddress((void**)&pattn,g_attn);
    cudaGetSymbolAddress((void**)&ptmp, g_tmp);
    cudaGetSymbolAddress((void**)&pffn, g_ffn);
    cudaGetSymbolAddress((void**)&pqg0, g_qg0);

    k_embed<<<NTOK, 256>>>(ids, wemb, pemb, elns, elnb, px);

    dim3 g768(HID / 128, NTOK / 128);
    dim3 g3072(FFNDIM / 128, NTOK / 128);

    for (int l = 0; l < 2; l++) {
        size_t ow  = (size_t)l * HID * HID;
        size_t ob  = (size_t)l * HID;
        size_t ow1 = (size_t)l * HID * FFNDIM;
        size_t ob1 = (size_t)l * FFNDIM;

        k_sgemm<0><<<g768, 256>>>(px, Wq  + ow, bq  + ob, pq,  NTOK, HID, HID);
        k_sgemm<0><<<g768, 256>>>(px, Wk  + ow, bk  + ob, pk,  NTOK, HID, HID);
        k_sgemm<0><<<g768, 256>>>(px, Wv  + ow, bv  + ob, pv,  NTOK, HID, HID);
        k_sgemm<0><<<g768, 256>>>(px, Wkg + ow, bkg + ob, pkg, NTOK, HID, HID);
        k_sgemm<0><<<g768, 256>>>(px, Wvg + ow, bvg + ob, pvg, NTOK, HID, HID);
        k_qg0<<<dim3(3, BB), 256>>>(px, Wqg + ow, bqg + ob, pqg0);

        k_band<<<dim3(NC, HEADS, BB), 256>>>(pq, pk, pv, pkg, pvg, am, pattn);
        k_glob<<<BB * HEADS, 256>>>(pqg0, pkg, pvg, am, pattn);

        k_sgemm<0><<<g768, 256>>>(pattn, Wo + ow, bo + ob, ptmp, NTOK, HID, HID);
        k_addln<<<NTOK, 256>>>(ptmp, ln1s + ob, ln1b + ob, px);

        k_sgemm<1><<<g3072, 256>>>(px, W1 + ow1, b1 + ob1, pffn, NTOK, FFNDIM, HID);
        k_sgemm<0><<<g768, 256>>>(pffn, W2 + ow1, b2 + ob, ptmp, NTOK, HID, FFNDIM);
        k_addln<<<NTOK, 256>>>(ptmp, ln2s + ob, ln2b + ob, px);
    }

    k_head<<<dim3((NLAB + 127) / 128, BB), 128>>>(px, hW, hb, out);
}

// round 2
// speedup vs baseline: 1.1708x; 1.1708x over previous
#include <cuda_runtime.h>
#include <math.h>

#define HID 768
#define HEADS 12
#define DH 64
#define WW 256
#define NC 16
#define FFNDIM 3072
#define NLAB 8921
#define BB 2
#define SS 4096
#define NTOK (BB*SS)

// -------- scratch (device globals; no allocation allowed) --------
__device__ float g_x[NTOK*HID];
__device__ float g_q[NTOK*HID];
__device__ float g_k[NTOK*HID];
__device__ float g_v[NTOK*HID];
__device__ float g_kg[NTOK*HID];
__device__ float g_vg[NTOK*HID];
__device__ float g_attn[NTOK*HID];
__device__ float g_tmp[NTOK*HID];
__device__ float g_ffn[NTOK*FFNDIM];
__device__ float g_qg0[BB*HID];

// -------- block reduction helpers (256 threads) --------
__device__ __forceinline__ float blk_sum256(float v, float* red) {
    #pragma unroll
    for (int o = 16; o > 0; o >>= 1) v += __shfl_xor_sync(0xffffffffu, v, o);
    int w = threadIdx.x >> 5, ln = threadIdx.x & 31;
    if (ln == 0) red[w] = v;
    __syncthreads();
    if (w == 0) {
        float t = (ln < 8) ? red[ln] : 0.0f;
        #pragma unroll
        for (int o = 4; o > 0; o >>= 1) t += __shfl_xor_sync(0xffffffffu, t, o);
        if (ln == 0) red[0] = t;
    }
    __syncthreads();
    float r = red[0];
    __syncthreads();
    return r;
}

__device__ __forceinline__ float blk_max256(float v, float* red) {
    #pragma unroll
    for (int o = 16; o > 0; o >>= 1) v = fmaxf(v, __shfl_xor_sync(0xffffffffu, v, o));
    int w = threadIdx.x >> 5, ln = threadIdx.x & 31;
    if (ln == 0) red[w] = v;
    __syncthreads();
    if (w == 0) {
        float t = (ln < 8) ? red[ln] : -3.0e38f;
        #pragma unroll
        for (int o = 4; o > 0; o >>= 1) t = fmaxf(t, __shfl_xor_sync(0xffffffffu, t, o));
        if (ln == 0) red[0] = t;
    }
    __syncthreads();
    float r = red[0];
    __syncthreads();
    return r;
}

// -------- embedding + LN --------
__global__ __launch_bounds__(256) void k_embed(
    const int* __restrict__ ids, const float* __restrict__ wemb,
    const float* __restrict__ pemb, const float* __restrict__ lns,
    const float* __restrict__ lnb, float* __restrict__ xout)
{
    __shared__ float red[32];
    int row = blockIdx.x;
    int tid = threadIdx.x;
    int s = row & (SS - 1);
    int id = ids[row];
    const float* we = wemb + (size_t)id * HID;
    const float* pe = pemb + (size_t)s * HID;
    float v0 = we[tid]       + pe[tid];
    float v1 = we[tid + 256] + pe[tid + 256];
    float v2 = we[tid + 512] + pe[tid + 512];
    float mean = blk_sum256(v0 + v1 + v2, red) * (1.0f / HID);
    v0 -= mean; v1 -= mean; v2 -= mean;
    float var = blk_sum256(v0*v0 + v1*v1 + v2*v2, red) * (1.0f / HID);
    float r = rsqrtf(var + 1e-5f);
    size_t base = (size_t)row * HID;
    xout[base + tid]       = v0 * r * lns[tid]       + lnb[tid];
    xout[base + tid + 256] = v1 * r * lns[tid + 256] + lnb[tid + 256];
    xout[base + tid + 512] = v2 * r * lns[tid + 512] + lnb[tid + 512];
}

// -------- residual add + LN (in-place on x) --------
__global__ __launch_bounds__(256) void k_addln(
    const float* __restrict__ add, const float* __restrict__ lns,
    const float* __restrict__ lnb, float* __restrict__ x)
{
    __shared__ float red[32];
    int row = blockIdx.x;
    int tid = threadIdx.x;
    size_t base = (size_t)row * HID;
    float v0 = x[base + tid]       + add[base + tid];
    float v1 = x[base + tid + 256] + add[base + tid + 256];
    float v2 = x[base + tid + 512] + add[base + tid + 512];
    float mean = blk_sum256(v0 + v1 + v2, red) * (1.0f / HID);
    v0 -= mean; v1 -= mean; v2 -= mean;
    float var = blk_sum256(v0*v0 + v1*v1 + v2*v2, red) * (1.0f / HID);
    float r = rsqrtf(var + 1e-5f);
    x[base + tid]       = v0 * r * lns[tid]       + lnb[tid];
    x[base + tid + 256] = v1 * r * lns[tid + 256] + lnb[tid + 256];
    x[base + tid + 512] = v2 * r * lns[tid + 512] + lnb[tid + 512];
}

// ==================== double-buffered SGEMM core ====================
// C[M,N] = A[M,K] @ W[K,N] + bias, optional exact GELU.
// BM=BN=128, BK=16, 256 threads, 8x8 per-thread tile, smem double buffer.
template <int ACT>
__device__ __forceinline__ void gemm_core(
    const float* __restrict__ A, const float* __restrict__ Bw,
    const float* __restrict__ bias, float* __restrict__ C,
    int N, int K, int bx, int by,
    float As[2][16][128], float Bs[2][16][128])
{
    const int BM = 128, BN = 128, BK = 16, TM = 8, TN = 8;
    int tid = threadIdx.x;

    // A load mapping: row = tid&127 (conflict-free STS), cols (tid>>7)*8 .. +7
    int aRow = tid & 127;
    int aCol = (tid >> 7) << 3;
    const float* aPtr = A + (size_t)(by * BM + aRow) * K + aCol;

    // B load mapping: row = tid>>4 (0..15), cols (tid&15)*4 and +64
    int bRow = tid >> 4;
    int bCol = (tid & 15) << 2;
    const float* bPtr = Bw + (size_t)bRow * N + bx * BN + bCol;

    int tRow = (tid >> 4) << 3;
    int tCol = (tid & 15) << 3;

    float acc[TM][TN];
    #pragma unroll
    for (int i = 0; i < TM; i++)
        #pragma unroll
        for (int j = 0; j < TN; j++) acc[i][j] = 0.0f;

    // ---- prologue: load tile 0 into buffer 0 ----
    {
        float4 a0 = *reinterpret_cast<const float4*>(aPtr);
        float4 a1 = *reinterpret_cast<const float4*>(aPtr + 4);
        float4 b0 = *reinterpret_cast<const float4*>(bPtr);
        float4 b1 = *reinterpret_cast<const float4*>(bPtr + 64);
        As[0][aCol + 0][aRow] = a0.x;
        As[0][aCol + 1][aRow] = a0.y;
        As[0][aCol + 2][aRow] = a0.z;
        As[0][aCol + 3][aRow] = a0.w;
        As[0][aCol + 4][aRow] = a1.x;
        As[0][aCol + 5][aRow] = a1.y;
        As[0][aCol + 6][aRow] = a1.z;
        As[0][aCol + 7][aRow] = a1.w;
        *reinterpret_cast<float4*>(&Bs[0][bRow][bCol])      = b0;
        *reinterpret_cast<float4*>(&Bs[0][bRow][bCol + 64]) = b1;
    }
    __syncthreads();

    int T = K / BK;
    for (int t = 0; t < T; ++t) {
        int buf = t & 1;
        float4 na0, na1, nb0, nb1;
        if (t + 1 < T) {
            const float* ap = aPtr + (size_t)(t + 1) * BK;
            const float* bp = bPtr + (size_t)(t + 1) * BK * N;
            na0 = *reinterpret_cast<const float4*>(ap);
            na1 = *reinterpret_cast<const float4*>(ap + 4);
            nb0 = *reinterpret_cast<const float4*>(bp);
            nb1 = *reinterpret_cast<const float4*>(bp + 64);
        }
        #pragma unroll
        for (int kk = 0; kk < BK; kk++) {
            float regM[TM], regN[TN];
            *reinterpret_cast<float4*>(&regM[0]) = *reinterpret_cast<const float4*>(&As[buf][kk][tRow]);
            *reinterpret_cast<float4*>(&regM[4]) = *reinterpret_cast<const float4*>(&As[buf][kk][tRow + 4]);
            *reinterpret_cast<float4*>(&regN[0]) = *reinterpret_cast<const float4*>(&Bs[buf][kk][tCol]);
            *reinterpret_cast<float4*>(&regN[4]) = *reinterpret_cast<const float4*>(&Bs[buf][kk][tCol + 4]);
            #pragma unroll
            for (int i = 0; i < TM; i++)
                #pragma unroll
                for (int j = 0; j < TN; j++)
                    acc[i][j] = fmaf(regM[i], regN[j], acc[i][j]);
        }
        if (t + 1 < T) {
            int nb = buf ^ 1;
            As[nb][aCol + 0][aRow] = na0.x;
            As[nb][aCol + 1][aRow] = na0.y;
            As[nb][aCol + 2][aRow] = na0.z;
            As[nb][aCol + 3][aRow] = na0.w;
            As[nb][aCol + 4][aRow] = na1.x;
            As[nb][aCol + 5][aRow] = na1.y;
            As[nb][aCol + 6][aRow] = na1.z;
            As[nb][aCol + 7][aRow] = na1.w;
            *reinterpret_cast<float4*>(&Bs[nb][bRow][bCol])      = nb0;
            *reinterpret_cast<float4*>(&Bs[nb][bRow][bCol + 64]) = nb1;
            __syncthreads();
        }
    }

    float* Cb = C + (size_t)by * BM * N + (size_t)bx * BN;
    const float* bb = bias + (size_t)bx * BN;
    #pragma unroll
    for (int i = 0; i < TM; i++) {
        #pragma unroll
        for (int j = 0; j < TN; j++) {
            float cv = acc[i][j] + bb[tCol + j];
            if (ACT == 1) cv = 0.5f * cv * (1.0f + erff(cv * 0.70710678118654752440f));
            acc[i][j] = cv;
        }
        #pragma unroll
        for (int j = 0; j < TN; j += 4) {
            float4 o = make_float4(acc[i][j], acc[i][j+1], acc[i][j+2], acc[i][j+3]);
            *reinterpret_cast<float4*>(Cb + (size_t)(tRow + i) * N + tCol + j) = o;
        }
    }
}

template <int ACT>
__global__ __launch_bounds__(256, 2) void k_sgemm(
    const float* __restrict__ A, const float* __restrict__ Bw,
    const float* __restrict__ bias, float* __restrict__ C, int N, int K)
{
    __shared__ float As[2][16][128];
    __shared__ float Bs[2][16][128];
    gemm_core<ACT>(A, Bw, bias, C, N, K, blockIdx.x, blockIdx.y, As, Bs);
}

// batched variant: 5 weight/bias/output triples sharing the same A (blockIdx.z selects)
struct Batch5 {
    const float* W[5];
    const float* b[5];
    float* C[5];
};

__global__ __launch_bounds__(256, 2) void k_sgemm5(
    const float* __restrict__ A, Batch5 bt, int N, int K)
{
    __shared__ float As[2][16][128];
    __shared__ float Bs[2][16][128];
    int z = blockIdx.z;
    gemm_core<0>(A, bt.W[z], bt.b[z], bt.C[z], N, K, blockIdx.x, blockIdx.y, As, Bs);
}

// -------- qg projection for CLS token only --------
__global__ __launch_bounds__(256) void k_qg0(
    const float* __restrict__ x, const float* __restrict__ Wg,
    const float* __restrict__ bg, float* __restrict__ outq)
{
    int b = blockIdx.y;
    int n = blockIdx.x * 256 + threadIdx.x;
    __shared__ float xs[HID];
    for (int i = threadIdx.x; i < HID; i += 256) xs[i] = x[(size_t)b * SS * HID + i];
    __syncthreads();
    float acc = bg[n];
    for (int kk = 0; kk < HID; kk++) acc = fmaf(xs[kk], Wg[(size_t)kk * HID + n], acc);
    outq[b * HID + n] = acc;
}

// -------- banded sliding-window attention + global-key column (online softmax) --------
#define KT 32
__global__ __launch_bounds__(256) void k_band(
    const float* __restrict__ q, const float* __restrict__ k,
    const float* __restrict__ v, const float* __restrict__ kg,
    const float* __restrict__ vg, const int* __restrict__ am,
    float* __restrict__ out)
{
    int c = blockIdx.x, h = blockIdx.y, b = blockIdx.z;
    int p = threadIdx.x;               // one query per thread
    int tid = threadIdx.x;
    int qpos = c * WW + p;
    int cstart = (c - 1) * WW;

    __shared__ float4 ks[KT][16];
    __shared__ float4 vs[KT][16];
    __shared__ float kg0[DH], vg0[DH];
    __shared__ unsigned char kval[3 * WW];

    if (tid < DH) {
        kg0[tid] = kg[(size_t)(b * SS) * HID + h * DH + tid];
        vg0[tid] = vg[(size_t)(b * SS) * HID + h * DH + tid];
    }
    for (int j = tid; j < 3 * WW; j += 256) {
        int kp = cstart + j;
        kval[j] = (kp > 0 && kp < SS && am[b * SS + kp] > 0) ? 1 : 0;
    }
    float4 qv[16];
    {
        const float4* qp4 = reinterpret_cast<const float4*>(
            q + (size_t)(b * SS + qpos) * HID + h * DH);
        #pragma unroll
        for (int i = 0; i < 16; i++) qv[i] = qp4[i];
    }
    __syncthreads();

    float m;
    {
        float acc = 0.0f;
        #pragma unroll
        for (int i = 0; i < 16; i++) {
            float4 k4 = reinterpret_cast<const float4*>(kg0)[i];
            acc += qv[i].x * k4.x + qv[i].y * k4.y + qv[i].z * k4.z + qv[i].w * k4.w;
        }
        m = acc * 0.125f;
    }
    float l = 1.0f;
    float4 accv[16];
    #pragma unroll
    for (int i = 0; i < 16; i++) accv[i] = reinterpret_cast<const float4*>(vg0)[i];

    for (int kt0 = 0; kt0 < 3 * WW; kt0 += KT) {
        __syncthreads();
        for (int t = tid; t < KT * 16; t += 256) {
            int jj = t >> 4, dd = t & 15;
            int kp = cstart + kt0 + jj;
            float4 kv4 = make_float4(0, 0, 0, 0), vv4 = make_float4(0, 0, 0, 0);
            if (kp >= 0 && kp < SS) {
                size_t base = (size_t)(b * SS + kp) * HID + h * DH;
                kv4 = *reinterpret_cast<const float4*>(k + base + dd * 4);
                vv4 = *reinterpret_cast<const float4*>(v + base + dd * 4);
            }
            ks[jj][dd] = kv4;
            vs[jj][dd] = vv4;
        }
        __syncthreads();
        int jlo = max(p - kt0, 0);
        int jhi = min(p + 2 * WW - kt0, KT - 1);
        for (int jj = jlo; jj <= jhi; jj++) {
            int j = kt0 + jj;
            if (!kval[j]) continue;
            float acc = 0.0f;
            #pragma unroll
            for (int i = 0; i < 16; i++) {
                float4 k4 = ks[jj][i];
                acc += qv[i].x * k4.x + qv[i].y * k4.y + qv[i].z * k4.z + qv[i].w * k4.w;
            }
            float sscore = acc * 0.125f;
            float mnew = fmaxf(m, sscore);
            float fac = __expf(m - mnew);
            float wgt = __expf(sscore - mnew);
            l = l * fac + wgt;
            #pragma unroll
            for (int i = 0; i < 16; i++) {
                float4 vv4 = vs[jj][i];
                accv[i].x = accv[i].x * fac + wgt * vv4.x;
                accv[i].y = accv[i].y * fac + wgt * vv4.y;
                accv[i].z = accv[i].z * fac + wgt * vv4.z;
                accv[i].w = accv[i].w * fac + wgt * vv4.w;
            }
            m = mnew;
        }
    }
    float inv = 1.0f / l;
    float4* op4 = reinterpret_cast<float4*>(out + (size_t)(b * SS + qpos) * HID + h * DH);
    #pragma unroll
    for (int i = 0; i < 16; i++) {
        accv[i].x *= inv; accv[i].y *= inv; accv[i].z *= inv; accv[i].w *= inv;
        op4[i] = accv[i];
    }
}

// -------- global (CLS) query: full attention over all S tokens, overwrites row 0 --------
__global__ __launch_bounds__(256) void k_glob(
    const float* __restrict__ qg0, const float* __restrict__ kg,
    const float* __restrict__ vg, const int* __restrict__ am,
    float* __restrict__ out)
{
    int b = blockIdx.x / HEADS;
    int h = blockIdx.x % HEADS;
    int tid = threadIdx.x;
    __shared__ float sc[SS];
    __shared__ float q0[DH];
    __shared__ float red[32];
    __shared__ float part[4][DH];

    if (tid < DH) q0[tid] = qg0[b * HID + h * DH + tid];
    __syncthreads();

    float lmax = -3.0e38f;
    for (int j = tid; j < SS; j += 256) {
        float sv = -1e9f;
        if (am[b * SS + j] > 0) {
            const float4* kr = reinterpret_cast<const float4*>(
                kg + (size_t)(b * SS + j) * HID + h * DH);
            float acc = 0.0f;
            #pragma unroll
            for (int i = 0; i < 16; i++) {
                float4 k4 = kr[i];
                float4 q4 = reinterpret_cast<const float4*>(q0)[i];
                acc += q4.x * k4.x + q4.y * k4.y + q4.z * k4.z + q4.w * k4.w;
            }
            sv = acc * 0.125f;
        }
        sc[j] = sv;
        lmax = fmaxf(lmax, sv);
    }
    float mm = blk_max256(lmax, red);
    float ls = 0.0f;
    for (int j = tid; j < SS; j += 256) {
        float w = __expf(sc[j] - mm);
        sc[j] = w;
        ls += w;
    }
    float sum = blk_sum256(ls, red);
    __syncthreads();

    int d = tid & 63, g = tid >> 6;
    float acc = 0.0f;
    for (int j = g; j < SS; j += 4)
        acc = fmaf(sc[j], vg[(size_t)(b * SS + j) * HID + h * DH + d], acc);
    part[g][d] = acc;
    __syncthreads();
    if (tid < DH) {
        float o = (part[0][tid] + part[1][tid] + part[2][tid] + part[3][tid]) / sum;
        out[(size_t)(b * SS) * HID + h * DH + tid] = o;
    }
}

// -------- classifier head --------
__global__ __launch_bounds__(128) void k_head(
    const float* __restrict__ x, const float* __restrict__ hw,
    const float* __restrict__ hb, float* __restrict__ out)
{
    int b = blockIdx.y;
    int n = blockIdx.x * 128 + threadIdx.x;
    __shared__ float xs[HID];
    for (int i = threadIdx.x; i < HID; i += 128) xs[i] = x[(size_t)b * SS * HID + i];
    __syncthreads();
    if (n >= NLAB) return;
    float acc = hb[n];
    for (int kk = 0; kk < HID; kk++) acc = fmaf(xs[kk], hw[(size_t)kk * NLAB + n], acc);
    out[b * NLAB + n] = acc;
}

// -------- orchestration --------
extern "C" void kernel_launch(void* const* d_in, const int* in_sizes, int n_in,
                              void* d_out, int out_size)
{
    const int*   ids  = (const int*)d_in[0];
    const int*   am   = (const int*)d_in[1];
    const float* wemb = (const float*)d_in[2];
    const float* pemb = (const float*)d_in[3];
    const float* elns = (const float*)d_in[4];
    const float* elnb = (const float*)d_in[5];
    const float* Wq   = (const float*)d_in[6];
    const float* bq   = (const float*)d_in[7];
    const float* Wk   = (const float*)d_in[8];
    const float* bk   = (const float*)d_in[9];
    const float* Wv   = (const float*)d_in[10];
    const float* bv   = (const float*)d_in[11];
    const float* Wqg  = (const float*)d_in[12];
    const float* bqg  = (const float*)d_in[13];
    const float* Wkg  = (const float*)d_in[14];
    const float* bkg  = (const float*)d_in[15];
    const float* Wvg  = (const float*)d_in[16];
    const float* bvg  = (const float*)d_in[17];
    const float* Wo   = (const float*)d_in[18];
    const float* bo   = (const float*)d_in[19];
    const float* ln1s = (const float*)d_in[20];
    const float* ln1b = (const float*)d_in[21];
    const float* W1   = (const float*)d_in[22];
    const float* b1   = (const float*)d_in[23];
    const float* W2   = (const float*)d_in[24];
    const float* b2   = (const float*)d_in[25];
    const float* ln2s = (const float*)d_in[26];
    const float* ln2b = (const float*)d_in[27];
    const float* hW   = (const float*)d_in[28];
    const float* hb   = (const float*)d_in[29];
    float* out = (float*)d_out;

    float *px, *pq, *pk, *pv, *pkg, *pvg, *pattn, *ptmp, *pffn, *pqg0;
    cudaGetSymbolAddress((void**)&px,   g_x);
    cudaGetSymbolAddress((void**)&pq,   g_q);
    cudaGetSymbolAddress((void**)&pk,   g_k);
    cudaGetSymbolAddress((void**)&pv,   g_v);
    cudaGetSymbolAddress((void**)&pkg,  g_kg);
    cudaGetSymbolAddress((void**)&pvg,  g_vg);
    cudaGetSymbolAddress((void**)&pattn,g_attn);
    cudaGetSymbolAddress((void**)&ptmp, g_tmp);
    cudaGetSymbolAddress((void**)&pffn, g_ffn);
    cudaGetSymbolAddress((void**)&pqg0, g_qg0);

    k_embed<<<NTOK, 256>>>(ids, wemb, pemb, elns, elnb, px);

    dim3 g768(HID / 128, NTOK / 128);
    dim3 g3072(FFNDIM / 128, NTOK / 128);
    dim3 gb5(HID / 128, NTOK / 128, 5);

    for (int l = 0; l < 2; l++) {
        size_t ow  = (size_t)l * HID * HID;
        size_t ob  = (size_t)l * HID;
        size_t ow1 = (size_t)l * HID * FFNDIM;
        size_t ob1 = (size_t)l * FFNDIM;

        Batch5 bt;
        bt.W[0] = Wq  + ow; bt.b[0] = bq  + ob; bt.C[0] = pq;
        bt.W[1] = Wk  + ow; bt.b[1] = bk  + ob; bt.C[1] = pk;
        bt.W[2] = Wv  + ow; bt.b[2] = bv  + ob; bt.C[2] = pv;
        bt.W[3] = Wkg + ow; bt.b[3] = bkg + ob; bt.C[3] = pkg;
        bt.W[4] = Wvg + ow; bt.b[4] = bvg + ob; bt.C[4] = pvg;

        k_sgemm5<<<gb5, 256>>>(px, bt, HID, HID);
        k_qg0<<<dim3(3, BB), 256>>>(px, Wqg + ow, bqg + ob, pqg0);

        k_band<<<dim3(NC, HEADS, BB), 256>>>(pq, pk, pv, pkg, pvg, am, pattn);
        k_glob<<<BB * HEADS, 256>>>(pqg0, pkg, pvg, am, pattn);

        k_sgemm<0><<<g768, 256>>>(pattn, Wo + ow, bo + ob, ptmp, HID, HID);
        k_addln<<<NTOK, 256>>>(ptmp, ln1s + ob, ln1b + ob, px);

        k_sgemm<1><<<g3072, 256>>>(px, W1 + ow1, b1 + ob1, pffn, FFNDIM, HID);
        k_sgemm<0><<<g768, 256>>>(pffn, W2 + ow1, b2 + ob, ptmp, HID, FFNDIM);
        k_addln<<<NTOK, 256>>>(ptmp, ln2s + ob, ln2b + ob, px);
    }

    k_head<<<dim3((NLAB + 127) / 128, BB), 128>>>(px, hW, hb, out);
}

// round 4
// speedup vs baseline: 1.4024x; 1.1978x over previous
#include <cuda_runtime.h>
#include <cuda_bf16.h>
#include <math.h>
#include <stdint.h>

#define HID 768
#define HEADS 12
#define DH 64
#define WW 256
#define NC 16
#define FFNDIM 3072
#define NLAB 8921
#define BB 2
#define SS 4096
#define NTOK (BB*SS)
#define K2P (3*HID)      // 2304 split-K for K=768
#define K2F (3*FFNDIM)   // 9216 split-K for K=3072

// -------- scratch (device globals; no allocation allowed) --------
__device__ __align__(256) float g_x[NTOK*HID];
__device__ __align__(256) float g_q[NTOK*HID];
__device__ __align__(256) float g_k[NTOK*HID];
__device__ __align__(256) float g_v[NTOK*HID];
__device__ __align__(256) float g_kg[NTOK*HID];
__device__ __align__(256) float g_vg[NTOK*HID];
__device__ __align__(256) float g_attn[NTOK*HID];
__device__ __align__(256) float g_tmp[NTOK*HID];
__device__ __align__(256) float g_ffn[NTOK*FFNDIM];
__device__ __align__(256) float g_qg0[BB*HID];
// bf16 split operands
__device__ __align__(256) __nv_bfloat16 g_wt[2*6*HID*K2P];     // 6 HIDxHID weights transposed+split
__device__ __align__(256) __nv_bfloat16 g_w1t[2*(size_t)FFNDIM*K2P];
__device__ __align__(256) __nv_bfloat16 g_w2t[2*(size_t)HID*K2F];
__device__ __align__(256) __nv_bfloat16 g_ab[(size_t)NTOK*K2F]; // activation split buffer

// ==================== small helpers ====================
__device__ __forceinline__ uint32_t s2u(const void* p) {
    uint32_t a;
    asm("{ .reg .u64 t; cvta.to.shared.u64 t, %1; cvt.u32.u64 %0, t; }" : "=r"(a) : "l"(p));
    return a;
}
__device__ __forceinline__ void cp16(uint32_t s, const void* g) {
    asm volatile("cp.async.cg.shared.global [%0], [%1], 16;" :: "r"(s), "l"(g));
}
__device__ __forceinline__ void ldsm4(uint32_t* r, uint32_t addr) {
    asm volatile("ldmatrix.sync.aligned.m8n8.x4.shared.b16 {%0,%1,%2,%3}, [%4];"
        : "=r"(r[0]), "=r"(r[1]), "=r"(r[2]), "=r"(r[3]) : "r"(addr));
}
__device__ __forceinline__ void mma_bf16(float* d, const uint32_t* a, uint32_t b0, uint32_t b1) {
    asm volatile(
        "mma.sync.aligned.m16n8k16.row.col.f32.bf16.bf16.f32 "
        "{%0,%1,%2,%3}, {%4,%5,%6,%7}, {%8,%9}, {%0,%1,%2,%3};"
        : "+f"(d[0]), "+f"(d[1]), "+f"(d[2]), "+f"(d[3])
        : "r"(a[0]), "r"(a[1]), "r"(a[2]), "r"(a[3]), "r"(b0), "r"(b1));
}

// -------- block reduction helpers (256 threads) --------
__device__ __forceinline__ float blk_sum256(float v, float* red) {
    #pragma unroll
    for (int o = 16; o > 0; o >>= 1) v += __shfl_xor_sync(0xffffffffu, v, o);
    int w = threadIdx.x >> 5, ln = threadIdx.x & 31;
    if (ln == 0) red[w] = v;
    __syncthreads();
    if (w == 0) {
        float t = (ln < 8) ? red[ln] : 0.0f;
        #pragma unroll
        for (int o = 4; o > 0; o >>= 1) t += __shfl_xor_sync(0xffffffffu, t, o);
        if (ln == 0) red[0] = t;
    }
    __syncthreads();
    float r = red[0];
    __syncthreads();
    return r;
}
__device__ __forceinline__ float blk_max256(float v, float* red) {
    #pragma unroll
    for (int o = 16; o > 0; o >>= 1) v = fmaxf(v, __shfl_xor_sync(0xffffffffu, v, o));
    int w = threadIdx.x >> 5, ln = threadIdx.x & 31;
    if (ln == 0) red[w] = v;
    __syncthreads();
    if (w == 0) {
        float t = (ln < 8) ? red[ln] : -3.0e38f;
        #pragma unroll
        for (int o = 4; o > 0; o >>= 1) t = fmaxf(t, __shfl_xor_sync(0xffffffffu, t, o));
        if (ln == 0) red[0] = t;
    }
    __syncthreads();
    float r = red[0];
    __syncthreads();
    return r;
}

// ==================== conversion kernels ====================
// W[K,N] fp32 -> O[N,3K] bf16 split (hi | lo | hi), transposed
__global__ __launch_bounds__(256) void k_cvtw(
    const float* __restrict__ W, __nv_bfloat16* __restrict__ O, int K, int N)
{
    __shared__ float tile[32][33];
    int k0 = blockIdx.x * 32, n0 = blockIdx.y * 32;
    int tx = threadIdx.x & 31, ty = threadIdx.x >> 5;
    #pragma unroll
    for (int j = 0; j < 32; j += 8)
        tile[ty + j][tx] = W[(size_t)(k0 + ty + j) * N + n0 + tx];
    __syncthreads();
    #pragma unroll
    for (int j = 0; j < 32; j += 8) {
        int n = n0 + ty + j, k = k0 + tx;
        float a = tile[tx][ty + j];
        __nv_bfloat16 hi = __float2bfloat16(a);
        __nv_bfloat16 lo = __float2bfloat16(a - __bfloat162float(hi));
        size_t base = (size_t)n * 3 * K;
        O[base + k] = hi;
        O[base + K + k] = lo;
        O[base + 2 * K + k] = hi;
    }
}

// A[M,K] fp32 -> O[M,3K] bf16 split (hi | hi | lo)
__global__ __launch_bounds__(256) void k_cvta(
    const float* __restrict__ A, __nv_bfloat16* __restrict__ O, int K)
{
    int m = blockIdx.y;
    int k = blockIdx.x * 256 + threadIdx.x;
    float a = A[(size_t)m * K + k];
    __nv_bfloat16 hi = __float2bfloat16(a);
    __nv_bfloat16 lo = __float2bfloat16(a - __bfloat162float(hi));
    size_t base = (size_t)m * 3 * K;
    O[base + k] = hi;
    O[base + K + k] = hi;
    O[base + 2 * K + k] = lo;
}

// ==================== bf16 mma.sync GEMM ====================
// C[M,N] = A'[M,K2] @ B'[N,K2]^T + bias (fp32 out), 128x128 CTA tile.
struct TcB {
    const __nv_bfloat16* W[5];
    const float* b[5];
    float* C[5];
};

#define RSB 80                 // padded smem row stride in bytes (40 bf16)
#define TBY (128*RSB)          // 10240 bytes per matrix per stage
#define MM_STG 3
#define MM_SMEM (MM_STG*2*TBY) // 61440

template <int ACT>
__global__ __launch_bounds__(256) void k_wmma(
    const __nv_bfloat16* __restrict__ A, TcB bt, int N, int K2)
{
    extern __shared__ char smem[];
    const int z = blockIdx.z;
    const __nv_bfloat16* Bw = bt.W[z];
    const float* bias = bt.b[z];
    float* C = bt.C[z];
    const int m0 = blockIdx.y * 128, n0 = blockIdx.x * 128;
    int tid = threadIdx.x, lane = tid & 31, wid = tid >> 5;
    int wm = wid & 3, wn = wid >> 2;
    uint32_t sb = s2u(smem);

    // cp.async mapping: thread -> row (tid&127), chunk pair ((tid>>7) and +2)
    int lr = tid & 127;
    int lc = tid >> 7;                 // 0/1 -> chunks lc and lc+2
    const char* gA = (const char*)(A + (size_t)(m0 + lr) * K2);
    const char* gB = (const char*)(Bw + (size_t)(n0 + lr) * K2);
    uint32_t st0 = (uint32_t)(lr * RSB + lc * 16);
    uint32_t st1 = st0 + 32;
    uint32_t gc0 = lc * 16, gc1 = gc0 + 32;

    float acc[2][8][4];
    #pragma unroll
    for (int i = 0; i < 2; i++)
        #pragma unroll
        for (int j = 0; j < 8; j++)
            #pragma unroll
            for (int c = 0; c < 4; c++) acc[i][j][c] = 0.0f;

    int NIT = K2 >> 5;   // K2/32

    auto issue = [&](int it) {
        int b = it % MM_STG;
        uint32_t base = sb + b * (2 * TBY);
        size_t go = (size_t)it * 64;  // 32 bf16 = 64 bytes along K
        cp16(base + st0, gA + go + gc0);
        cp16(base + st1, gA + go + gc1);
        cp16(base + TBY + st0, gB + go + gc0);
        cp16(base + TBY + st1, gB + go + gc1);
        asm volatile("cp.async.commit_group;" ::: "memory");
    };
    issue(0); issue(1);

    int lrow = lane & 15, lk8 = lane >> 4;   // ldmatrix row / k-half select
    uint32_t aRowOff = (uint32_t)((wm * 32 + lrow) * RSB + lk8 * 16);
    uint32_t bRowOff = (uint32_t)((wn * 64 + lrow) * RSB + lk8 * 16);

    for (int it = 0; it < NIT; it++) {
        if (it == NIT - 1) asm volatile("cp.async.wait_group 0;" ::: "memory");
        else               asm volatile("cp.async.wait_group 1;" ::: "memory");
        __syncthreads();
        if (it + 2 < NIT) issue(it + 2);

        int b = it % MM_STG;
        uint32_t aBase = sb + b * (2 * TBY) + aRowOff;
        uint32_t bBase = sb + b * (2 * TBY) + TBY + bRowOff;
        #pragma unroll
        for (int kk = 0; kk < 2; kk++) {          // two k16 halves of BK=32
            uint32_t ar[2][4], br[4][4];
            #pragma unroll
            for (int mf = 0; mf < 2; mf++)
                ldsm4(ar[mf], aBase + mf * (16 * RSB) + kk * 32);
            #pragma unroll
            for (int nf = 0; nf < 4; nf++)
                ldsm4(br[nf], bBase + nf * (16 * RSB) + kk * 32);
            #pragma unroll
            for (int mf = 0; mf < 2; mf++)
                #pragma unroll
                for (int ns = 0; ns < 8; ns++)
                    mma_bf16(acc[mf][ns], ar[mf],
                             br[ns >> 1][ns & 1], br[ns >> 1][(ns & 1) + 2]);
        }
    }

    // epilogue: direct global stores (float2 per fragment row)
    int erow = lane >> 2, ecol = (lane & 3) * 2;
    #pragma unroll
    for (int mf = 0; mf < 2; mf++) {
        int r0 = m0 + wm * 32 + mf * 16 + erow;
        #pragma unroll
        for (int ns = 0; ns < 8; ns++) {
            int cc = n0 + wn * 64 + ns * 8 + ecol;
            float b0 = bias[cc], b1 = bias[cc + 1];
            float v0 = acc[mf][ns][0] + b0;
            float v1 = acc[mf][ns][1] + b1;
            float v2 = acc[mf][ns][2] + b0;
            float v3 = acc[mf][ns][3] + b1;
            if (ACT == 1) {
                v0 = 0.5f * v0 * (1.0f + erff(v0 * 0.70710678118654752440f));
                v1 = 0.5f * v1 * (1.0f + erff(v1 * 0.70710678118654752440f));
                v2 = 0.5f * v2 * (1.0f + erff(v2 * 0.70710678118654752440f));
                v3 = 0.5f * v3 * (1.0f + erff(v3 * 0.70710678118654752440f));
            }
            *reinterpret_cast<float2*>(&C[(size_t)r0 * N + cc])       = make_float2(v0, v1);
            *reinterpret_cast<float2*>(&C[(size_t)(r0 + 8) * N + cc]) = make_float2(v2, v3);
        }
    }
}

// ==================== non-GEMM kernels ====================
__global__ __launch_bounds__(256) void k_embed(
    const int* __restrict__ ids, const float* __restrict__ wemb,
    const float* __restrict__ pemb, const float* __restrict__ lns,
    const float* __restrict__ lnb, float* __restrict__ xout)
{
    __shared__ float red[32];
    int row = blockIdx.x;
    int tid = threadIdx.x;
    int s = row & (SS - 1);
    int id = ids[row];
    const float* we = wemb + (size_t)id * HID;
    const float* pe = pemb + (size_t)s * HID;
    float v0 = we[tid]       + pe[tid];
    float v1 = we[tid + 256] + pe[tid + 256];
    float v2 = we[tid + 512] + pe[tid + 512];
    float mean = blk_sum256(v0 + v1 + v2, red) * (1.0f / HID);
    v0 -= mean; v1 -= mean; v2 -= mean;
    float var = blk_sum256(v0*v0 + v1*v1 + v2*v2, red) * (1.0f / HID);
    float r = rsqrtf(var + 1e-5f);
    size_t base = (size_t)row * HID;
    xout[base + tid]       = v0 * r * lns[tid]       + lnb[tid];
    xout[base + tid + 256] = v1 * r * lns[tid + 256] + lnb[tid + 256];
    xout[base + tid + 512] = v2 * r * lns[tid + 512] + lnb[tid + 512];
}

__global__ __launch_bounds__(256) void k_addln(
    const float* __restrict__ add, const float* __restrict__ lns,
    const float* __restrict__ lnb, float* __restrict__ x)
{
    __shared__ float red[32];
    int row = blockIdx.x;
    int tid = threadIdx.x;
    size_t base = (size_t)row * HID;
    float v0 = x[base + tid]       + add[base + tid];
    float v1 = x[base + tid + 256] + add[base + tid + 256];
    float v2 = x[base + tid + 512] + add[base + tid + 512];
    float mean = blk_sum256(v0 + v1 + v2, red) * (1.0f / HID);
    v0 -= mean; v1 -= mean; v2 -= mean;
    float var = blk_sum256(v0*v0 + v1*v1 + v2*v2, red) * (1.0f / HID);
    float r = rsqrtf(var + 1e-5f);
    x[base + tid]       = v0 * r * lns[tid]       + lnb[tid];
    x[base + tid + 256] = v1 * r * lns[tid + 256] + lnb[tid + 256];
    x[base + tid + 512] = v2 * r * lns[tid + 512] + lnb[tid + 512];
}

__global__ __launch_bounds__(256) void k_qg0(
    const float* __restrict__ x, const float* __restrict__ Wg,
    const float* __restrict__ bg, float* __restrict__ outq)
{
    int b = blockIdx.y;
    int n = blockIdx.x * 256 + threadIdx.x;
    __shared__ float xs[HID];
    for (int i = threadIdx.x; i < HID; i += 256) xs[i] = x[(size_t)b * SS * HID + i];
    __syncthreads();
    float acc = bg[n];
    for (int kk = 0; kk < HID; kk++) acc = fmaf(xs[kk], Wg[(size_t)kk * HID + n], acc);
    outq[b * HID + n] = acc;
}

#define KT 32
__global__ __launch_bounds__(256) void k_band(
    const float* __restrict__ q, const float* __restrict__ k,
    const float* __restrict__ v, const float* __restrict__ kg,
    const float* __restrict__ vg, const int* __restrict__ am,
    float* __restrict__ out)
{
    int c = blockIdx.x, h = blockIdx.y, b = blockIdx.z;
    int p = threadIdx.x;
    int tid = threadIdx.x;
    int qpos = c * WW + p;
    int cstart = (c - 1) * WW;

    __shared__ float4 ks[KT][16];
    __shared__ float4 vs[KT][16];
    __shared__ float kg0[DH], vg0[DH];
    __shared__ unsigned char kval[3 * WW];

    if (tid < DH) {
        kg0[tid] = kg[(size_t)(b * SS) * HID + h * DH + tid];
        vg0[tid] = vg[(size_t)(b * SS) * HID + h * DH + tid];
    }
    for (int j = tid; j < 3 * WW; j += 256) {
        int kp = cstart + j;
        kval[j] = (kp > 0 && kp < SS && am[b * SS + kp] > 0) ? 1 : 0;
    }
    float4 qv[16];
    {
        const float4* qp4 = reinterpret_cast<const float4*>(
            q + (size_t)(b * SS + qpos) * HID + h * DH);
        #pragma unroll
        for (int i = 0; i < 16; i++) qv[i] = qp4[i];
    }
    __syncthreads();

    float m;
    {
        float acc = 0.0f;
        #pragma unroll
        for (int i = 0; i < 16; i++) {
            float4 k4 = reinterpret_cast<const float4*>(kg0)[i];
            acc += qv[i].x * k4.x + qv[i].y * k4.y + qv[i].z * k4.z + qv[i].w * k4.w;
        }
        m = acc * 0.125f;
    }
    float l = 1.0f;
    float4 accv[16];
    #pragma unroll
    for (int i = 0; i < 16; i++) accv[i] = reinterpret_cast<const float4*>(vg0)[i];

    for (int kt0 = 0; kt0 < 3 * WW; kt0 += KT) {
        __syncthreads();
        for (int t = tid; t < KT * 16; t += 256) {
            int jj = t >> 4, dd = t & 15;
            int kp = cstart + kt0 + jj;
            float4 kv4 = make_float4(0, 0, 0, 0), vv4 = make_float4(0, 0, 0, 0);
            if (kp >= 0 && kp < SS) {
                size_t base = (size_t)(b * SS + kp) * HID + h * DH;
                kv4 = *reinterpret_cast<const float4*>(k + base + dd * 4);
                vv4 = *reinterpret_cast<const float4*>(v + base + dd * 4);
            }
            ks[jj][dd] = kv4;
            vs[jj][dd] = vv4;
        }
        __syncthreads();
        int jlo = max(p - kt0, 0);
        int jhi = min(p + 2 * WW - kt0, KT - 1);
        for (int jj = jlo; jj <= jhi; jj++) {
            int j = kt0 + jj;
            if (!kval[j]) continue;
            float acc = 0.0f;
            #pragma unroll
            for (int i = 0; i < 16; i++) {
                float4 k4 = ks[jj][i];
                acc += qv[i].x * k4.x + qv[i].y * k4.y + qv[i].z * k4.z + qv[i].w * k4.w;
            }
            float sscore = acc * 0.125f;
            float mnew = fmaxf(m, sscore);
            float fac = __expf(m - mnew);
            float wgt = __expf(sscore - mnew);
            l = l * fac + wgt;
            #pragma unroll
            for (int i = 0; i < 16; i++) {
                float4 vv4 = vs[jj][i];
                accv[i].x = accv[i].x * fac + wgt * vv4.x;
                accv[i].y = accv[i].y * fac + wgt * vv4.y;
                accv[i].z = accv[i].z * fac + wgt * vv4.z;
                accv[i].w = accv[i].w * fac + wgt * vv4.w;
            }
            m = mnew;
        }
    }
    float inv = 1.0f / l;
    float4* op4 = reinterpret_cast<float4*>(out + (size_t)(b * SS + qpos) * HID + h * DH);
    #pragma unroll
    for (int i = 0; i < 16; i++) {
        accv[i].x *= inv; accv[i].y *= inv; accv[i].z *= inv; accv[i].w *= inv;
        op4[i] = accv[i];
    }
}

__global__ __launch_bounds__(256) void k_glob(
    const float* __restrict__ qg0, const float* __restrict__ kg,
    const float* __restrict__ vg, const int* __restrict__ am,
    float* __restrict__ out)
{
    int b = blockIdx.x / HEADS;
    int h = blockIdx.x % HEADS;
    int tid = threadIdx.x;
    __shared__ float sc[SS];
    __shared__ float q0[DH];
    __shared__ float red[32];
    __shared__ float part[4][DH];

    if (tid < DH) q0[tid] = qg0[b * HID + h * DH + tid];
    __syncthreads();

    float lmax = -3.0e38f;
    for (int j = tid; j < SS; j += 256) {
        float sv = -1e9f;
        if (am[b * SS + j] > 0) {
            const float4* kr = reinterpret_cast<const float4*>(
                kg + (size_t)(b * SS + j) * HID + h * DH);
            float acc = 0.0f;
            #pragma unroll
            for (int i = 0; i < 16; i++) {
                float4 k4 = kr[i];
                float4 q4 = reinterpret_cast<const float4*>(q0)[i];
                acc += q4.x * k4.x + q4.y * k4.y + q4.z * k4.z + q4.w * k4.w;
            }
            sv = acc * 0.125f;
        }
        sc[j] = sv;
        lmax = fmaxf(lmax, sv);
    }
    float mm = blk_max256(lmax, red);
    float ls = 0.0f;
    for (int j = tid; j < SS; j += 256) {
        float w = __expf(sc[j] - mm);
        sc[j] = w;
        ls += w;
    }
    float sum = blk_sum256(ls, red);
    __syncthreads();

    int d = tid & 63, g = tid >> 6;
    float acc = 0.0f;
    for (int j = g; j < SS; j += 4)
        acc = fmaf(sc[j], vg[(size_t)(b * SS + j) * HID + h * DH + d], acc);
    part[g][d] = acc;
    __syncthreads();
    if (tid < DH) {
        float o = (part[0][tid] + part[1][tid] + part[2][tid] + part[3][tid]) / sum;
        out[(size_t)(b * SS) * HID + h * DH + tid] = o;
    }
}

__global__ __launch_bounds__(128) void k_head(
    const float* __restrict__ x, const float* __restrict__ hw,
    const float* __restrict__ hb, float* __restrict__ out)
{
    int b = blockIdx.y;
    int n = blockIdx.x * 128 + threadIdx.x;
    __shared__ float xs[HID];
    for (int i = threadIdx.x; i < HID; i += 128) xs[i] = x[(size_t)b * SS * HID + i];
    __syncthreads();
    if (n >= NLAB) return;
    float acc = hb[n];
    for (int kk = 0; kk < HID; kk++) acc = fmaf(xs[kk], hw[(size_t)kk * NLAB + n], acc);
    out[b * NLAB + n] = acc;
}

// ==================== orchestration ====================
extern "C" void kernel_launch(void* const* d_in, const int* in_sizes, int n_in,
                              void* d_out, int out_size)
{
    const int*   ids  = (const int*)d_in[0];
    const int*   am   = (const int*)d_in[1];
    const float* wemb = (const float*)d_in[2];
    const float* pemb = (const float*)d_in[3];
    const float* elns = (const float*)d_in[4];
    const float* elnb = (const float*)d_in[5];
    const float* Wq   = (const float*)d_in[6];
    const float* bq   = (const float*)d_in[7];
    const float* Wk   = (const float*)d_in[8];
    const float* bk   = (const float*)d_in[9];
    const float* Wv   = (const float*)d_in[10];
    const float* bv   = (const float*)d_in[11];
    const float* Wqg  = (const float*)d_in[12];
    const float* bqg  = (const float*)d_in[13];
    const float* Wkg  = (const float*)d_in[14];
    const float* bkg  = (const float*)d_in[15];
    const float* Wvg  = (const float*)d_in[16];
    const float* bvg  = (const float*)d_in[17];
    const float* Wo   = (const float*)d_in[18];
    const float* bo   = (const float*)d_in[19];
    const float* ln1s = (const float*)d_in[20];
    const float* ln1b = (const float*)d_in[21];
    const float* W1   = (const float*)d_in[22];
    const float* b1   = (const float*)d_in[23];
    const float* W2   = (const float*)d_in[24];
    const float* b2   = (const float*)d_in[25];
    const float* ln2s = (const float*)d_in[26];
    const float* ln2b = (const float*)d_in[27];
    const float* hW   = (const float*)d_in[28];
    const float* hb   = (const float*)d_in[29];
    float* out = (float*)d_out;

    float *px, *pq, *pk, *pv, *pkg, *pvg, *pattn, *ptmp, *pffn, *pqg0;
    __nv_bfloat16 *pwt, *pw1t, *pw2t, *pab;
    cudaGetSymbolAddress((void**)&px,   g_x);
    cudaGetSymbolAddress((void**)&pq,   g_q);
    cudaGetSymbolAddress((void**)&pk,   g_k);
    cudaGetSymbolAddress((void**)&pv,   g_v);
    cudaGetSymbolAddress((void**)&pkg,  g_kg);
    cudaGetSymbolAddress((void**)&pvg,  g_vg);
    cudaGetSymbolAddress((void**)&pattn,g_attn);
    cudaGetSymbolAddress((void**)&ptmp, g_tmp);
    cudaGetSymbolAddress((void**)&pffn, g_ffn);
    cudaGetSymbolAddress((void**)&pqg0, g_qg0);
    cudaGetSymbolAddress((void**)&pwt,  g_wt);
    cudaGetSymbolAddress((void**)&pw1t, g_w1t);
    cudaGetSymbolAddress((void**)&pw2t, g_w2t);
    cudaGetSymbolAddress((void**)&pab,  g_ab);

    cudaFuncSetAttribute(k_wmma<0>, cudaFuncAttributeMaxDynamicSharedMemorySize, MM_SMEM);
    cudaFuncSetAttribute(k_wmma<1>, cudaFuncAttributeMaxDynamicSharedMemorySize, MM_SMEM);

    // ---- weight conversions (deterministic; run every launch) ----
    for (int l = 0; l < 2; l++) {
        size_t ow  = (size_t)l * HID * HID;
        size_t ow1 = (size_t)l * HID * FFNDIM;
        const float* Ws[6] = {Wq + ow, Wk + ow, Wv + ow, Wkg + ow, Wvg + ow, Wo + ow};
        for (int i = 0; i < 6; i++)
            k_cvtw<<<dim3(HID / 32, HID / 32), 256>>>(
                Ws[i], pwt + ((size_t)(l * 6 + i)) * HID * K2P, HID, HID);
        k_cvtw<<<dim3(HID / 32, FFNDIM / 32), 256>>>(W1 + ow1, pw1t + (size_t)l * FFNDIM * K2P, HID, FFNDIM);
        k_cvtw<<<dim3(FFNDIM / 32, HID / 32), 256>>>(W2 + ow1, pw2t + (size_t)l * HID * K2F, FFNDIM, HID);
    }

    k_embed<<<NTOK, 256>>>(ids, wemb, pemb, elns, elnb, px);

    for (int l = 0; l < 2; l++) {
        size_t ow  = (size_t)l * HID * HID;
        size_t ob  = (size_t)l * HID;
        size_t ob1 = (size_t)l * FFNDIM;
        const __nv_bfloat16* wl = pwt + (size_t)(l * 6) * HID * K2P;

        // x -> split; 5 projections batched
        k_cvta<<<dim3(HID / 256, NTOK), 256>>>(px, pab, HID);
        {
            TcB b5;
            b5.W[0] = wl + 0 * (size_t)HID * K2P; b5.b[0] = bq  + ob; b5.C[0] = pq;
            b5.W[1] = wl + 1 * (size_t)HID * K2P; b5.b[1] = bk  + ob; b5.C[1] = pk;
            b5.W[2] = wl + 2 * (size_t)HID * K2P; b5.b[2] = bv  + ob; b5.C[2] = pv;
            b5.W[3] = wl + 3 * (size_t)HID * K2P; b5.b[3] = bkg + ob; b5.C[3] = pkg;
            b5.W[4] = wl + 4 * (size_t)HID * K2P; b5.b[4] = bvg + ob; b5.C[4] = pvg;
            k_wmma<0><<<dim3(HID / 128, NTOK / 128, 5), 256, MM_SMEM>>>(pab, b5, HID, K2P);
        }
        k_qg0<<<dim3(3, BB), 256>>>(px, Wqg + ow, bqg + ob, pqg0);

        k_band<<<dim3(NC, HEADS, BB), 256>>>(pq, pk, pv, pkg, pvg, am, pattn);
        k_glob<<<BB * HEADS, 256>>>(pqg0, pkg, pvg, am, pattn);

        // attn @ Wo
        k_cvta<<<dim3(HID / 256, NTOK), 256>>>(pattn, pab, HID);
        {
            TcB bo5; bo5.W[0] = wl + 5 * (size_t)HID * K2P; bo5.b[0] = bo + ob; bo5.C[0] = ptmp;
            k_wmma<0><<<dim3(HID / 128, NTOK / 128, 1), 256, MM_SMEM>>>(pab, bo5, HID, K2P);
        }
        k_addln<<<NTOK, 256>>>(ptmp, ln1s + ob, ln1b + ob, px);

        // FFN
        k_cvta<<<dim3(HID / 256, NTOK), 256>>>(px, pab, HID);
        {
            TcB bw1; bw1.W[0] = pw1t + (size_t)l * FFNDIM * K2P; bw1.b[0] = b1 + ob1; bw1.C[0] = pffn;
            k_wmma<1><<<dim3(FFNDIM / 128, NTOK / 128, 1), 256, MM_SMEM>>>(pab, bw1, FFNDIM, K2P);
        }
        k_cvta<<<dim3(FFNDIM / 256, NTOK), 256>>>(pffn, pab, FFNDIM);
        {
            TcB bw2; bw2.W[0] = pw2t + (size_t)l * HID * K2F; bw2.b[0] = b2 + ob; bw2.C[0] = ptmp;
            k_wmma<0><<<dim3(HID / 128, NTOK / 128, 1), 256, MM_SMEM>>>(pab, bw2, HID, K2F);
        }
        k_addln<<<NTOK, 256>>>(ptmp, ln2s + ob, ln2b + ob, px);
    }

    k_head<<<dim3((NLAB + 127) / 128, BB), 128>>>(px, hW, hb, out);
}

// round 5
// speedup vs baseline: 1.4113x; 1.0064x over previous
#include <cuda_runtime.h>
#include <cuda_bf16.h>
#include <math.h>
#include <stdint.h>

#define HID 768
#define HEADS 12
#define DH 64
#define WW 256
#define NC 16
#define FFNDIM 3072
#define NLAB 8921
#define BB 2
#define SS 4096
#define NTOK (BB*SS)

// -------- scratch (device globals; no allocation allowed) --------
__device__ __align__(256) float g_x[NTOK*HID];
__device__ __align__(256) float g_q[NTOK*HID];
__device__ __align__(256) float g_k[NTOK*HID];
__device__ __align__(256) float g_v[NTOK*HID];
__device__ __align__(256) float g_kg[NTOK*HID];
__device__ __align__(256) float g_vg[NTOK*HID];
__device__ __align__(256) float g_attn[NTOK*HID];
__device__ __align__(256) float g_tmp[NTOK*HID];
__device__ __align__(256) float g_ffn[NTOK*FFNDIM];
__device__ __align__(256) float g_qg0[BB*HID];
// bf16 split operands, compact [hi | lo] layout (row stride 2K)
__device__ __align__(256) __nv_bfloat16 g_wt[(size_t)2*6*HID*2*HID];
__device__ __align__(256) __nv_bfloat16 g_w1t[(size_t)2*FFNDIM*2*HID];
__device__ __align__(256) __nv_bfloat16 g_w2t[(size_t)2*HID*2*FFNDIM];
__device__ __align__(256) __nv_bfloat16 g_ab[(size_t)NTOK*2*FFNDIM];

// ==================== small helpers ====================
__device__ __forceinline__ uint32_t s2u(const void* p) {
    uint32_t a;
    asm("{ .reg .u64 t; cvta.to.shared.u64 t, %1; cvt.u32.u64 %0, t; }" : "=r"(a) : "l"(p));
    return a;
}
__device__ __forceinline__ void cp16(uint32_t s, const void* g) {
    asm volatile("cp.async.cg.shared.global [%0], [%1], 16;" :: "r"(s), "l"(g));
}
__device__ __forceinline__ void ldsm4(uint32_t* r, uint32_t addr) {
    asm volatile("ldmatrix.sync.aligned.m8n8.x4.shared.b16 {%0,%1,%2,%3}, [%4];"
        : "=r"(r[0]), "=r"(r[1]), "=r"(r[2]), "=r"(r[3]) : "r"(addr));
}
__device__ __forceinline__ void mma_bf16(float* d, const uint32_t* a, uint32_t b0, uint32_t b1) {
    asm volatile(
        "mma.sync.aligned.m16n8k16.row.col.f32.bf16.bf16.f32 "
        "{%0,%1,%2,%3}, {%4,%5,%6,%7}, {%8,%9}, {%0,%1,%2,%3};"
        : "+f"(d[0]), "+f"(d[1]), "+f"(d[2]), "+f"(d[3])
        : "r"(a[0]), "r"(a[1]), "r"(a[2]), "r"(a[3]), "r"(b0), "r"(b1));
}

// -------- block reduction helpers (256 threads) --------
__device__ __forceinline__ float blk_sum256(float v, float* red) {
    #pragma unroll
    for (int o = 16; o > 0; o >>= 1) v += __shfl_xor_sync(0xffffffffu, v, o);
    int w = threadIdx.x >> 5, ln = threadIdx.x & 31;
    if (ln == 0) red[w] = v;
    __syncthreads();
    if (w == 0) {
        float t = (ln < 8) ? red[ln] : 0.0f;
        #pragma unroll
        for (int o = 4; o > 0; o >>= 1) t += __shfl_xor_sync(0xffffffffu, t, o);
        if (ln == 0) red[0] = t;
    }
    __syncthreads();
    float r = red[0];
    __syncthreads();
    return r;
}
__device__ __forceinline__ float blk_max256(float v, float* red) {
    #pragma unroll
    for (int o = 16; o > 0; o >>= 1) v = fmaxf(v, __shfl_xor_sync(0xffffffffu, v, o));
    int w = threadIdx.x >> 5, ln = threadIdx.x & 31;
    if (ln == 0) red[w] = v;
    __syncthreads();
    if (w == 0) {
        float t = (ln < 8) ? red[ln] : -3.0e38f;
        #pragma unroll
        for (int o = 4; o > 0; o >>= 1) t = fmaxf(t, __shfl_xor_sync(0xffffffffu, t, o));
        if (ln == 0) red[0] = t;
    }
    __syncthreads();
    float r = red[0];
    __syncthreads();
    return r;
}

// ==================== conversion kernels ====================
// W[K,N] fp32 -> O[N,2K] bf16 transposed, [hi | lo]
__global__ __launch_bounds__(256) void k_cvtw(
    const float* __restrict__ W, __nv_bfloat16* __restrict__ O, int K, int N)
{
    __shared__ float tile[32][33];
    int k0 = blockIdx.x * 32, n0 = blockIdx.y * 32;
    int tx = threadIdx.x & 31, ty = threadIdx.x >> 5;
    #pragma unroll
    for (int j = 0; j < 32; j += 8)
        tile[ty + j][tx] = W[(size_t)(k0 + ty + j) * N + n0 + tx];
    __syncthreads();
    #pragma unroll
    for (int j = 0; j < 32; j += 8) {
        int n = n0 + ty + j, k = k0 + tx;
        float a = tile[tx][ty + j];
        __nv_bfloat16 hi = __float2bfloat16(a);
        __nv_bfloat16 lo = __float2bfloat16(a - __bfloat162float(hi));
        size_t base = (size_t)n * 2 * K;
        O[base + k] = hi;
        O[base + K + k] = lo;
    }
}

// A[M,K] fp32 -> O[M,2K] bf16, [hi | lo]; thread = 4 consecutive elements
__global__ __launch_bounds__(256) void k_cvta(
    const float* __restrict__ A, __nv_bfloat16* __restrict__ O, int K)
{
    int idx = blockIdx.x * 256 + threadIdx.x;   // float4 index, contiguous
    int K4 = K >> 2;
    int m = idx / K4;
    int k4 = idx - m * K4;
    float4 a = reinterpret_cast<const float4*>(A)[idx];
    __nv_bfloat16 h[4], l[4];
    float av[4] = {a.x, a.y, a.z, a.w};
    #pragma unroll
    for (int i = 0; i < 4; i++) {
        h[i] = __float2bfloat16(av[i]);
        l[i] = __float2bfloat16(av[i] - __bfloat162float(h[i]));
    }
    size_t base = (size_t)m * 2 * K + 4 * k4;
    *reinterpret_cast<uint2*>(O + base)     = *reinterpret_cast<uint2*>(h);
    *reinterpret_cast<uint2*>(O + base + K) = *reinterpret_cast<uint2*>(l);
}

// ==================== bf16 mma.sync GEMM, virtual 3-segment split-K ====================
// C[M,N] = sum over segs { A_hi.B_hi + A_hi.B_lo + A_lo.B_hi } + bias
// A, B stored [hi|lo] with row stride 2K. 128x128 CTA tile, BK=64, 3-stage cp.async.
struct TcB {
    const __nv_bfloat16* W[5];
    const float* b[5];
    float* C[5];
};

#define STG_BYTES 32768                // A 16KB + B 16KB per stage
#define MM_STG 3
#define MM_SMEM (MM_STG*STG_BYTES)     // 96KB

template <int ACT>
__global__ __launch_bounds__(256, 2) void k_wmma(
    const __nv_bfloat16* __restrict__ A, TcB bt, int N, int K)
{
    extern __shared__ char smem[];
    const int z = blockIdx.z;
    const __nv_bfloat16* Bw = bt.W[z];
    const float* bias = bt.b[z];
    float* C = bt.C[z];
    const int m0 = blockIdx.y * 128, n0 = blockIdx.x * 128;
    int tid = threadIdx.x, lane = tid & 31, wid = tid >> 5;
    int wm = wid & 3, wn = wid >> 2;
    uint32_t sb = s2u(smem);

    const int nchK = K >> 6;          // 64-elem chunks per physical segment
    const int NIT = 3 * nchK;

    // ---- cp.async mapping: row = tid&127, 4 chunks of 16B per matrix ----
    int lr = tid & 127;
    int half = tid >> 7;              // 0/1 -> chunks 0-3 / 4-7
    const char* gAr = (const char*)(A + (size_t)(m0 + lr) * 2 * K);
    const char* gBr = (const char*)(Bw + (size_t)(n0 + lr) * 2 * K);
    uint32_t stoff[4];
    uint32_t gcol[4];
    #pragma unroll
    for (int j = 0; j < 4; j++) {
        int c16 = half * 4 + j;
        stoff[j] = (uint32_t)(lr * 128 + ((c16 ^ (lr & 7)) << 4));
        gcol[j] = (uint32_t)(c16 << 4);
    }

    float acc[2][8][4];
    #pragma unroll
    for (int i = 0; i < 2; i++)
        #pragma unroll
        for (int j = 0; j < 8; j++)
            #pragma unroll
            for (int c = 0; c < 4; c++) acc[i][j][c] = 0.0f;

    // issue-state counters (advance in issue order)
    int iseg = 0, ioff = 0;
    auto issue = [&](int t) {
        int b = t % MM_STG;
        uint32_t base = sb + b * STG_BYTES;
        size_t aoff = (size_t)(iseg < 2 ? 0 : 2 * K) + (size_t)ioff * 128;  // bytes
        size_t boff = (size_t)(iseg == 1 ? 2 * K : 0) + (size_t)ioff * 128;
        #pragma unroll
        for (int j = 0; j < 4; j++) cp16(base + stoff[j], gAr + aoff + gcol[j]);
        #pragma unroll
        for (int j = 0; j < 4; j++) cp16(base + 16384 + stoff[j], gBr + boff + gcol[j]);
        asm volatile("cp.async.commit_group;" ::: "memory");
        if (++ioff == nchK) { ioff = 0; ++iseg; }
    };
    issue(0); issue(1);

    // ---- ldmatrix addressing (swizzled) ----
    int lrow = lane & 15, lk8 = lane >> 4, rxor = lrow & 7;
    uint32_t aRow = (uint32_t)((wm * 32 + lrow) * 128);
    uint32_t bRow = (uint32_t)((wn * 64 + lrow) * 128);
    uint32_t swz[4];
    #pragma unroll
    for (int kk = 0; kk < 4; kk++)
        swz[kk] = (uint32_t)((((kk * 2) + lk8) ^ rxor) << 4);

    for (int t = 0; t < NIT; t++) {
        if (t == NIT - 1) asm volatile("cp.async.wait_group 0;" ::: "memory");
        else              asm volatile("cp.async.wait_group 1;" ::: "memory");
        __syncthreads();
        if (t + 2 < NIT) issue(t + 2);

        int b = t % MM_STG;
        uint32_t aBase = sb + b * STG_BYTES + aRow;
        uint32_t bBase = sb + b * STG_BYTES + 16384 + bRow;
        #pragma unroll
        for (int kk = 0; kk < 4; kk++) {
            uint32_t ar[2][4], br[4][4];
            #pragma unroll
            for (int mf = 0; mf < 2; mf++)
                ldsm4(ar[mf], aBase + mf * (16 * 128) + swz[kk]);
            #pragma unroll
            for (int nf = 0; nf < 4; nf++)
                ldsm4(br[nf], bBase + nf * (16 * 128) + swz[kk]);
            #pragma unroll
            for (int mf = 0; mf < 2; mf++)
                #pragma unroll
                for (int ns = 0; ns < 8; ns++)
                    mma_bf16(acc[mf][ns], ar[mf],
                             br[ns >> 1][ns & 1], br[ns >> 1][(ns & 1) + 2]);
        }
    }

    // epilogue
    int erow = lane >> 2, ecol = (lane & 3) * 2;
    #pragma unroll
    for (int mf = 0; mf < 2; mf++) {
        int r0 = m0 + wm * 32 + mf * 16 + erow;
        #pragma unroll
        for (int ns = 0; ns < 8; ns++) {
            int cc = n0 + wn * 64 + ns * 8 + ecol;
            float b0 = bias[cc], b1 = bias[cc + 1];
            float v0 = acc[mf][ns][0] + b0;
            float v1 = acc[mf][ns][1] + b1;
            float v2 = acc[mf][ns][2] + b0;
            float v3 = acc[mf][ns][3] + b1;
            if (ACT == 1) {
                v0 = 0.5f * v0 * (1.0f + erff(v0 * 0.70710678118654752440f));
                v1 = 0.5f * v1 * (1.0f + erff(v1 * 0.70710678118654752440f));
                v2 = 0.5f * v2 * (1.0f + erff(v2 * 0.70710678118654752440f));
                v3 = 0.5f * v3 * (1.0f + erff(v3 * 0.70710678118654752440f));
            }
            *reinterpret_cast<float2*>(&C[(size_t)r0 * N + cc])       = make_float2(v0, v1);
            *reinterpret_cast<float2*>(&C[(size_t)(r0 + 8) * N + cc]) = make_float2(v2, v3);
        }
    }
}

// ==================== non-GEMM kernels ====================
__global__ __launch_bounds__(256) void k_embed(
    const int* __restrict__ ids, const float* __restrict__ wemb,
    const float* __restrict__ pemb, const float* __restrict__ lns,
    const float* __restrict__ lnb, float* __restrict__ xout)
{
    __shared__ float red[32];
    int row = blockIdx.x;
    int tid = threadIdx.x;
    int s = row & (SS - 1);
    int id = ids[row];
    const float* we = wemb + (size_t)id * HID;
    const float* pe = pemb + (size_t)s * HID;
    float v0 = we[tid]       + pe[tid];
    float v1 = we[tid + 256] + pe[tid + 256];
    float v2 = we[tid + 512] + pe[tid + 512];
    float mean = blk_sum256(v0 + v1 + v2, red) * (1.0f / HID);
    v0 -= mean; v1 -= mean; v2 -= mean;
    float var = blk_sum256(v0*v0 + v1*v1 + v2*v2, red) * (1.0f / HID);
    float r = rsqrtf(var + 1e-5f);
    size_t base = (size_t)row * HID;
    xout[base + tid]       = v0 * r * lns[tid]       + lnb[tid];
    xout[base + tid + 256] = v1 * r * lns[tid + 256] + lnb[tid + 256];
    xout[base + tid + 512] = v2 * r * lns[tid + 512] + lnb[tid + 512];
}

__global__ __launch_bounds__(256) void k_addln(
    const float* __restrict__ add, const float* __restrict__ lns,
    const float* __restrict__ lnb, float* __restrict__ x)
{
    __shared__ float red[32];
    int row = blockIdx.x;
    int tid = threadIdx.x;
    size_t base = (size_t)row * HID;
    float v0 = x[base + tid]       + add[base + tid];
    float v1 = x[base + tid + 256] + add[base + tid + 256];
    float v2 = x[base + tid + 512] + add[base + tid + 512];
    float mean = blk_sum256(v0 + v1 + v2, red) * (1.0f / HID);
    v0 -= mean; v1 -= mean; v2 -= mean;
    float var = blk_sum256(v0*v0 + v1*v1 + v2*v2, red) * (1.0f / HID);
    float r = rsqrtf(var + 1e-5f);
    x[base + tid]       = v0 * r * lns[tid]       + lnb[tid];
    x[base + tid + 256] = v1 * r * lns[tid + 256] + lnb[tid + 256];
    x[base + tid + 512] = v2 * r * lns[tid + 512] + lnb[tid + 512];
}

__global__ __launch_bounds__(256) void k_qg0(
    const float* __restrict__ x, const float* __restrict__ Wg,
    const float* __restrict__ bg, float* __restrict__ outq)
{
    int b = blockIdx.y;
    int n = blockIdx.x * 256 + threadIdx.x;
    __shared__ float xs[HID];
    for (int i = threadIdx.x; i < HID; i += 256) xs[i] = x[(size_t)b * SS * HID + i];
    __syncthreads();
    float acc = bg[n];
    for (int kk = 0; kk < HID; kk++) acc = fmaf(xs[kk], Wg[(size_t)kk * HID + n], acc);
    outq[b * HID + n] = acc;
}

#define KT 32
__global__ __launch_bounds__(256) void k_band(
    const float* __restrict__ q, const float* __restrict__ k,
    const float* __restrict__ v, const float* __restrict__ kg,
    const float* __restrict__ vg, const int* __restrict__ am,
    float* __restrict__ out)
{
    int c = blockIdx.x, h = blockIdx.y, b = blockIdx.z;
    int p = threadIdx.x;
    int tid = threadIdx.x;
    int qpos = c * WW + p;
    int cstart = (c - 1) * WW;

    __shared__ float4 ks[KT][16];
    __shared__ float4 vs[KT][16];
    __shared__ float kg0[DH], vg0[DH];
    __shared__ unsigned char kval[3 * WW];

    if (tid < DH) {
        kg0[tid] = kg[(size_t)(b * SS) * HID + h * DH + tid];
        vg0[tid] = vg[(size_t)(b * SS) * HID + h * DH + tid];
    }
    for (int j = tid; j < 3 * WW; j += 256) {
        int kp = cstart + j;
        kval[j] = (kp > 0 && kp < SS && am[b * SS + kp] > 0) ? 1 : 0;
    }
    float4 qv[16];
    {
        const float4* qp4 = reinterpret_cast<const float4*>(
            q + (size_t)(b * SS + qpos) * HID + h * DH);
        #pragma unroll
        for (int i = 0; i < 16; i++) qv[i] = qp4[i];
    }
    __syncthreads();

    float m;
    {
        float acc = 0.0f;
        #pragma unroll
        for (int i = 0; i < 16; i++) {
            float4 k4 = reinterpret_cast<const float4*>(kg0)[i];
            acc += qv[i].x * k4.x + qv[i].y * k4.y + qv[i].z * k4.z + qv[i].w * k4.w;
        }
        m = acc * 0.125f;
    }
    float l = 1.0f;
    float4 accv[16];
    #pragma unroll
    for (int i = 0; i < 16; i++) accv[i] = reinterpret_cast<const float4*>(vg0)[i];

    for (int kt0 = 0; kt0 < 3 * WW; kt0 += KT) {
        __syncthreads();
        for (int t = tid; t < KT * 16; t += 256) {
            int jj = t >> 4, dd = t & 15;
            int kp = cstart + kt0 + jj;
            float4 kv4 = make_float4(0, 0, 0, 0), vv4 = make_float4(0, 0, 0, 0);
            if (kp >= 0 && kp < SS) {
                size_t base = (size_t)(b * SS + kp) * HID + h * DH;
                kv4 = *reinterpret_cast<const float4*>(k + base + dd * 4);
                vv4 = *reinterpret_cast<const float4*>(v + base + dd * 4);
            }
            ks[jj][dd] = kv4;
            vs[jj][dd] = vv4;
        }
        __syncthreads();
        int jlo = max(p - kt0, 0);
        int jhi = min(p + 2 * WW - kt0, KT - 1);
        for (int jj = jlo; jj <= jhi; jj++) {
            int j = kt0 + jj;
            if (!kval[j]) continue;
            float acc = 0.0f;
            #pragma unroll
            for (int i = 0; i < 16; i++) {
                float4 k4 = ks[jj][i];
                acc += qv[i].x * k4.x + qv[i].y * k4.y + qv[i].z * k4.z + qv[i].w * k4.w;
            }
            float sscore = acc * 0.125f;
            float mnew = fmaxf(m, sscore);
            float fac = __expf(m - mnew);
            float wgt = __expf(sscore - mnew);
            l = l * fac + wgt;
            #pragma unroll
            for (int i = 0; i < 16; i++) {
                float4 vv4 = vs[jj][i];
                accv[i].x = accv[i].x * fac + wgt * vv4.x;
                accv[i].y = accv[i].y * fac + wgt * vv4.y;
                accv[i].z = accv[i].z * fac + wgt * vv4.z;
                accv[i].w = accv[i].w * fac + wgt * vv4.w;
            }
            m = mnew;
        }
    }
    float inv = 1.0f / l;
    float4* op4 = reinterpret_cast<float4*>(out + (size_t)(b * SS + qpos) * HID + h * DH);
    #pragma unroll
    for (int i = 0; i < 16; i++) {
        accv[i].x *= inv; accv[i].y *= inv; accv[i].z *= inv; accv[i].w *= inv;
        op4[i] = accv[i];
    }
}

__global__ __launch_bounds__(256) void k_glob(
    const float* __restrict__ qg0, const float* __restrict__ kg,
    const float* __restrict__ vg, const int* __restrict__ am,
    float* __restrict__ out)
{
    int b = blockIdx.x / HEADS;
    int h = blockIdx.x % HEADS;
    int tid = threadIdx.x;
    __shared__ float sc[SS];
    __shared__ float q0[DH];
    __shared__ float red[32];
    __shared__ float part[4][DH];

    if (tid < DH) q0[tid] = qg0[b * HID + h * DH + tid];
    __syncthreads();

    float lmax = -3.0e38f;
    for (int j = tid; j < SS; j += 256) {
        float sv = -1e9f;
        if (am[b * SS + j] > 0) {
            const float4* kr = reinterpret_cast<const float4*>(
                kg + (size_t)(b * SS + j) * HID + h * DH);
            float acc = 0.0f;
            #pragma unroll
            for (int i = 0; i < 16; i++) {
                float4 k4 = kr[i];
                float4 q4 = reinterpret_cast<const float4*>(q0)[i];
                acc += q4.x * k4.x + q4.y * k4.y + q4.z * k4.z + q4.w * k4.w;
            }
            sv = acc * 0.125f;
        }
        sc[j] = sv;
        lmax = fmaxf(lmax, sv);
    }
    float mm = blk_max256(lmax, red);
    float ls = 0.0f;
    for (int j = tid; j < SS; j += 256) {
        float w = __expf(sc[j] - mm);
        sc[j] = w;
        ls += w;
    }
    float sum = blk_sum256(ls, red);
    __syncthreads();

    int d = tid & 63, g = tid >> 6;
    float acc = 0.0f;
    for (int j = g; j < SS; j += 4)
        acc = fmaf(sc[j], vg[(size_t)(b * SS + j) * HID + h * DH + d], acc);
    part[g][d] = acc;
    __syncthreads();
    if (tid < DH) {
        float o = (part[0][tid] + part[1][tid] + part[2][tid] + part[3][tid]) / sum;
        out[(size_t)(b * SS) * HID + h * DH + tid] = o;
    }
}

__global__ __launch_bounds__(128) void k_head(
    const float* __restrict__ x, const float* __restrict__ hw,
    const float* __restrict__ hb, float* __restrict__ out)
{
    int b = blockIdx.y;
    int n = blockIdx.x * 128 + threadIdx.x;
    __shared__ float xs[HID];
    for (int i = threadIdx.x; i < HID; i += 128) xs[i] = x[(size_t)b * SS * HID + i];
    __syncthreads();
    if (n >= NLAB) return;
    float acc = hb[n];
    for (int kk = 0; kk < HID; kk++) acc = fmaf(xs[kk], hw[(size_t)kk * NLAB + n], acc);
    out[b * NLAB + n] = acc;
}

// ==================== orchestration ====================
extern "C" void kernel_launch(void* const* d_in, const int* in_sizes, int n_in,
                              void* d_out, int out_size)
{
    const int*   ids  = (const int*)d_in[0];
    const int*   am   = (const int*)d_in[1];
    const float* wemb = (const float*)d_in[2];
    const float* pemb = (const float*)d_in[3];
    const float* elns = (const float*)d_in[4];
    const float* elnb = (const float*)d_in[5];
    const float* Wq   = (const float*)d_in[6];
    const float* bq   = (const float*)d_in[7];
    const float* Wk   = (const float*)d_in[8];
    const float* bk   = (const float*)d_in[9];
    const float* Wv   = (const float*)d_in[10];
    const float* bv   = (const float*)d_in[11];
    const float* Wqg  = (const float*)d_in[12];
    const float* bqg  = (const float*)d_in[13];
    const float* Wkg  = (const float*)d_in[14];
    const float* bkg  = (const float*)d_in[15];
    const float* Wvg  = (const float*)d_in[16];
    const float* bvg  = (const float*)d_in[17];
    const float* Wo   = (const float*)d_in[18];
    const float* bo   = (const float*)d_in[19];
    const float* ln1s = (const float*)d_in[20];
    const float* ln1b = (const float*)d_in[21];
    const float* W1   = (const float*)d_in[22];
    const float* b1   = (const float*)d_in[23];
    const float* W2   = (const float*)d_in[24];
    const float* b2   = (const float*)d_in[25];
    const float* ln2s = (const float*)d_in[26];
    const float* ln2b = (const float*)d_in[27];
    const float* hW   = (const float*)d_in[28];
    const float* hb   = (const float*)d_in[29];
    float* out = (float*)d_out;

    float *px, *pq, *pk, *pv, *pkg, *pvg, *pattn, *ptmp, *pffn, *pqg0;
    __nv_bfloat16 *pwt, *pw1t, *pw2t, *pab;
    cudaGetSymbolAddress((void**)&px,   g_x);
    cudaGetSymbolAddress((void**)&pq,   g_q);
    cudaGetSymbolAddress((void**)&pk,   g_k);
    cudaGetSymbolAddress((void**)&pv,   g_v);
    cudaGetSymbolAddress((void**)&pkg,  g_kg);
    cudaGetSymbolAddress((void**)&pvg,  g_vg);
    cudaGetSymbolAddress((void**)&pattn,g_attn);
    cudaGetSymbolAddress((void**)&ptmp, g_tmp);
    cudaGetSymbolAddress((void**)&pffn, g_ffn);
    cudaGetSymbolAddress((void**)&pqg0, g_qg0);
    cudaGetSymbolAddress((void**)&pwt,  g_wt);
    cudaGetSymbolAddress((void**)&pw1t, g_w1t);
    cudaGetSymbolAddress((void**)&pw2t, g_w2t);
    cudaGetSymbolAddress((void**)&pab,  g_ab);

    cudaFuncSetAttribute(k_wmma<0>, cudaFuncAttributeMaxDynamicSharedMemorySize, MM_SMEM);
    cudaFuncSetAttribute(k_wmma<1>, cudaFuncAttributeMaxDynamicSharedMemorySize, MM_SMEM);

    const size_t WSTRIDE = (size_t)HID * 2 * HID;   // one converted weight matrix

    // ---- weight conversions ----
    for (int l = 0; l < 2; l++) {
        size_t ow  = (size_t)l * HID * HID;
        size_t ow1 = (size_t)l * HID * FFNDIM;
        const float* Ws[6] = {Wq + ow, Wk + ow, Wv + ow, Wkg + ow, Wvg + ow, Wo + ow};
        for (int i = 0; i < 6; i++)
            k_cvtw<<<dim3(HID / 32, HID / 32), 256>>>(Ws[i], pwt + (size_t)(l * 6 + i) * WSTRIDE, HID, HID);
        k_cvtw<<<dim3(HID / 32, FFNDIM / 32), 256>>>(W1 + ow1, pw1t + (size_t)l * FFNDIM * 2 * HID, HID, FFNDIM);
        k_cvtw<<<dim3(FFNDIM / 32, HID / 32), 256>>>(W2 + ow1, pw2t + (size_t)l * HID * 2 * FFNDIM, FFNDIM, HID);
    }

    k_embed<<<NTOK, 256>>>(ids, wemb, pemb, elns, elnb, px);

    const int CVT_H = NTOK * (HID / 4) / 256;     // 6144
    const int CVT_F = NTOK * (FFNDIM / 4) / 256;  // 24576

    for (int l = 0; l < 2; l++) {
        size_t ow  = (size_t)l * HID * HID;
        size_t ob  = (size_t)l * HID;
        size_t ob1 = (size_t)l * FFNDIM;
        const __nv_bfloat16* wl = pwt + (size_t)(l * 6) * WSTRIDE;

        // x -> split; 5 projections batched
        k_cvta<<<CVT_H, 256>>>(px, pab, HID);
        {
            TcB b5;
            b5.W[0] = wl + 0 * WSTRIDE; b5.b[0] = bq  + ob; b5.C[0] = pq;
            b5.W[1] = wl + 1 * WSTRIDE; b5.b[1] = bk  + ob; b5.C[1] = pk;
            b5.W[2] = wl + 2 * WSTRIDE; b5.b[2] = bv  + ob; b5.C[2] = pv;
            b5.W[3] = wl + 3 * WSTRIDE; b5.b[3] = bkg + ob; b5.C[3] = pkg;
            b5.W[4] = wl + 4 * WSTRIDE; b5.b[4] = bvg + ob; b5.C[4] = pvg;
            k_wmma<0><<<dim3(HID / 128, NTOK / 128, 5), 256, MM_SMEM>>>(pab, b5, HID, HID);
        }
        k_qg0<<<dim3(3, BB), 256>>>(px, Wqg + ow, bqg + ob, pqg0);

        k_band<<<dim3(NC, HEADS, BB), 256>>>(pq, pk, pv, pkg, pvg, am, pattn);
        k_glob<<<BB * HEADS, 256>>>(pqg0, pkg, pvg, am, pattn);

        // attn @ Wo
        k_cvta<<<CVT_H, 256>>>(pattn, pab, HID);
        {
            TcB bo5; bo5.W[0] = wl + 5 * WSTRIDE; bo5.b[0] = bo + ob; bo5.C[0] = ptmp;
            k_wmma<0><<<dim3(HID / 128, NTOK / 128, 1), 256, MM_SMEM>>>(pab, bo5, HID, HID);
        }
        k_addln<<<NTOK, 256>>>(ptmp, ln1s + ob, ln1b + ob, px);

        // FFN
        k_cvta<<<CVT_H, 256>>>(px, pab, HID);
        {
            TcB bw1; bw1.W[0] = pw1t + (size_t)l * FFNDIM * 2 * HID; bw1.b[0] = b1 + ob1; bw1.C[0] = pffn;
            k_wmma<1><<<dim3(FFNDIM / 128, NTOK / 128, 1), 256, MM_SMEM>>>(pab, bw1, FFNDIM, HID);
        }
        k_cvta<<<CVT_F, 256>>>(pffn, pab, FFNDIM);
        {
            TcB bw2; bw2.W[0] = pw2t + (size_t)l * HID * 2 * FFNDIM; bw2.b[0] = b2 + ob; bw2.C[0] = ptmp;
            k_wmma<0><<<dim3(HID / 128, NTOK / 128, 1), 256, MM_SMEM>>>(pab, bw2, HID, FFNDIM);
        }
        k_addln<<<NTOK, 256>>>(ptmp, ln2s + ob, ln2b + ob, px);
    }

    k_head<<<dim3((NLAB + 127) / 128, BB), 128>>>(px, hW, hb, out);
}

// round 6
// speedup vs baseline: 1.7520x; 1.2414x over previous
#include <cuda_runtime.h>
#include <cuda_fp16.h>
#include <math.h>
#include <stdint.h>

#define HID 768
#define HEADS 12
#define DH 64
#define WW 256
#define NC 16
#define FFNDIM 3072
#define NLAB 8921
#define BB 2
#define SS 4096
#define NTOK (BB*SS)

// -------- scratch (device globals; no allocation allowed) --------
__device__ __align__(256) float g_x[NTOK*HID];
__device__ __align__(256) float g_q[NTOK*HID];
__device__ __align__(256) float g_k[NTOK*HID];
__device__ __align__(256) float g_v[NTOK*HID];
__device__ __align__(256) float g_kg[NTOK*HID];
__device__ __align__(256) float g_vg[NTOK*HID];
__device__ __align__(256) float g_attn[NTOK*HID];
__device__ __align__(256) float g_tmp[NTOK*HID];
__device__ __align__(256) float g_qg0[BB*HID];
// fp16 operands: weights single-rounded (transposed), activations split [hi|lo]
__device__ __align__(256) __half g_wt[(size_t)2*6*HID*HID];
__device__ __align__(256) __half g_w1t[(size_t)2*FFNDIM*HID];
__device__ __align__(256) __half g_w2t[(size_t)2*HID*FFNDIM];
__device__ __align__(256) __half g_ab[(size_t)NTOK*2*FFNDIM];   // FFN intermediate split
__device__ __align__(256) __half g_ab2[(size_t)NTOK*2*HID];     // HID-wide splits

// ==================== small helpers ====================
__device__ __forceinline__ uint32_t s2u(const void* p) {
    uint32_t a;
    asm("{ .reg .u64 t; cvta.to.shared.u64 t, %1; cvt.u32.u64 %0, t; }" : "=r"(a) : "l"(p));
    return a;
}
__device__ __forceinline__ void cp16(uint32_t s, const void* g) {
    asm volatile("cp.async.cg.shared.global [%0], [%1], 16;" :: "r"(s), "l"(g));
}
__device__ __forceinline__ void ldsm4(uint32_t* r, uint32_t addr) {
    asm volatile("ldmatrix.sync.aligned.m8n8.x4.shared.b16 {%0,%1,%2,%3}, [%4];"
        : "=r"(r[0]), "=r"(r[1]), "=r"(r[2]), "=r"(r[3]) : "r"(addr));
}
__device__ __forceinline__ void mma_f16(float* d, const uint32_t* a, uint32_t b0, uint32_t b1) {
    asm volatile(
        "mma.sync.aligned.m16n8k16.row.col.f32.f16.f16.f32 "
        "{%0,%1,%2,%3}, {%4,%5,%6,%7}, {%8,%9}, {%0,%1,%2,%3};"
        : "+f"(d[0]), "+f"(d[1]), "+f"(d[2]), "+f"(d[3])
        : "r"(a[0]), "r"(a[1]), "r"(a[2]), "r"(a[3]), "r"(b0), "r"(b1));
}

// -------- block reduction helpers (256 threads) --------
__device__ __forceinline__ float blk_sum256(float v, float* red) {
    #pragma unroll
    for (int o = 16; o > 0; o >>= 1) v += __shfl_xor_sync(0xffffffffu, v, o);
    int w = threadIdx.x >> 5, ln = threadIdx.x & 31;
    if (ln == 0) red[w] = v;
    __syncthreads();
    if (w == 0) {
        float t = (ln < 8) ? red[ln] : 0.0f;
        #pragma unroll
        for (int o = 4; o > 0; o >>= 1) t += __shfl_xor_sync(0xffffffffu, t, o);
        if (ln == 0) red[0] = t;
    }
    __syncthreads();
    float r = red[0];
    __syncthreads();
    return r;
}
__device__ __forceinline__ float blk_max256(float v, float* red) {
    #pragma unroll
    for (int o = 16; o > 0; o >>= 1) v = fmaxf(v, __shfl_xor_sync(0xffffffffu, v, o));
    int w = threadIdx.x >> 5, ln = threadIdx.x & 31;
    if (ln == 0) red[w] = v;
    __syncthreads();
    if (w == 0) {
        float t = (ln < 8) ? red[ln] : -3.0e38f;
        #pragma unroll
        for (int o = 4; o > 0; o >>= 1) t = fmaxf(t, __shfl_xor_sync(0xffffffffu, t, o));
        if (ln == 0) red[0] = t;
    }
    __syncthreads();
    float r = red[0];
    __syncthreads();
    return r;
}

// ==================== conversion kernels ====================
// W[K,N] fp32 -> O[N,K] fp16 transposed (single rounding)
__global__ __launch_bounds__(256) void k_cvtw(
    const float* __restrict__ W, __half* __restrict__ O, int K, int N)
{
    __shared__ float tile[32][33];
    int k0 = blockIdx.x * 32, n0 = blockIdx.y * 32;
    int tx = threadIdx.x & 31, ty = threadIdx.x >> 5;
    #pragma unroll
    for (int j = 0; j < 32; j += 8)
        tile[ty + j][tx] = W[(size_t)(k0 + ty + j) * N + n0 + tx];
    __syncthreads();
    #pragma unroll
    for (int j = 0; j < 32; j += 8) {
        int n = n0 + ty + j, k = k0 + tx;
        O[(size_t)n * K + k] = __float2half(tile[tx][ty + j]);
    }
}

// A[M,K] fp32 -> O[M,2K] fp16 [hi | lo]; thread = 4 consecutive elements
__global__ __launch_bounds__(256) void k_cvta(
    const float* __restrict__ A, __half* __restrict__ O, int K)
{
    int idx = blockIdx.x * 256 + threadIdx.x;   // float4 index, contiguous
    int K4 = K >> 2;
    int m = idx / K4;
    int k4 = idx - m * K4;
    float4 a = reinterpret_cast<const float4*>(A)[idx];
    __half h[4], l[4];
    float av[4] = {a.x, a.y, a.z, a.w};
    #pragma unroll
    for (int i = 0; i < 4; i++) {
        h[i] = __float2half(av[i]);
        l[i] = __float2half(av[i] - __half2float(h[i]));
    }
    size_t base = (size_t)m * 2 * K + 4 * k4;
    *reinterpret_cast<uint2*>(O + base)     = *reinterpret_cast<uint2*>(h);
    *reinterpret_cast<uint2*>(O + base + K) = *reinterpret_cast<uint2*>(l);
}

// ==================== fp16 mma.sync GEMM, 2-term virtual split-K ====================
// C = A_hi.B + A_lo.B + bias. A stored [hi|lo] stride 2K; B fp16 stride K.
// ACT 0: fp32 out. ACT 1: GELU then write split fp16 [hi|lo] stride 2N.
struct TcB {
    const __half* W[5];
    const float* b[5];
    float* C[5];
};

#define STG_BYTES 32768                // A 16KB + B 16KB per stage
#define MM_STG 3
#define MM_SMEM (MM_STG*STG_BYTES)     // 96KB

template <int ACT>
__global__ __launch_bounds__(256, 2) void k_wmma(
    const __half* __restrict__ A, TcB bt, int N, int K)
{
    extern __shared__ char smem[];
    const int z = blockIdx.z;
    const __half* Bw = bt.W[z];
    const float* bias = bt.b[z];
    float* C = bt.C[z];
    const int m0 = blockIdx.y * 128, n0 = blockIdx.x * 128;
    int tid = threadIdx.x, lane = tid & 31, wid = tid >> 5;
    int wm = wid & 3, wn = wid >> 2;
    uint32_t sb = s2u(smem);

    const int nchK = K >> 6;          // 64-elem chunks per segment
    const int NIT = 2 * nchK;

    // ---- cp.async mapping: row = tid&127, 4 chunks of 16B per matrix ----
    int lr = tid & 127;
    int half_ = tid >> 7;             // 0/1 -> chunks 0-3 / 4-7
    const char* gAr = (const char*)(A + (size_t)(m0 + lr) * 2 * K);
    const char* gBr = (const char*)(Bw + (size_t)(n0 + lr) * K);
    uint32_t stoff[4];
    uint32_t gcol[4];
    #pragma unroll
    for (int j = 0; j < 4; j++) {
        int c16 = half_ * 4 + j;
        stoff[j] = (uint32_t)(lr * 128 + ((c16 ^ (lr & 7)) << 4));
        gcol[j] = (uint32_t)(c16 << 4);
    }

    float acc[2][8][4];
    #pragma unroll
    for (int i = 0; i < 2; i++)
        #pragma unroll
        for (int j = 0; j < 8; j++)
            #pragma unroll
            for (int c = 0; c < 4; c++) acc[i][j][c] = 0.0f;

    int iseg = 0, ioff = 0;           // issue-order counters
    auto issue = [&](int t) {
        int b = t % MM_STG;
        uint32_t base = sb + b * STG_BYTES;
        size_t aoff = (size_t)iseg * 2 * K + (size_t)ioff * 128;  // bytes
        size_t boff = (size_t)ioff * 128;
        #pragma unroll
        for (int j = 0; j < 4; j++) cp16(base + stoff[j], gAr + aoff + gcol[j]);
        #pragma unroll
        for (int j = 0; j < 4; j++) cp16(base + 16384 + stoff[j], gBr + boff + gcol[j]);
        asm volatile("cp.async.commit_group;" ::: "memory");
        if (++ioff == nchK) { ioff = 0; ++iseg; }
    };
    issue(0); issue(1);

    // ---- ldmatrix addressing (swizzled) ----
    int lrow = lane & 15, lk8 = lane >> 4, rxor = lrow & 7;
    uint32_t aRow = (uint32_t)((wm * 32 + lrow) * 128);
    uint32_t bRow = (uint32_t)((wn * 64 + lrow) * 128);
    uint32_t swz[4];
    #pragma unroll
    for (int kk = 0; kk < 4; kk++)
        swz[kk] = (uint32_t)((((kk * 2) + lk8) ^ rxor) << 4);

    for (int t = 0; t < NIT; t++) {
        if (t == NIT - 1) asm volatile("cp.async.wait_group 0;" ::: "memory");
        else              asm volatile("cp.async.wait_group 1;" ::: "memory");
        __syncthreads();
        if (t + 2 < NIT) issue(t + 2);

        int b = t % MM_STG;
        uint32_t aBase = sb + b * STG_BYTES + aRow;
        uint32_t bBase = sb + b * STG_BYTES + 16384 + bRow;
        #pragma unroll
        for (int kk = 0; kk < 4; kk++) {
            uint32_t ar[2][4], br[4][4];
            #pragma unroll
            for (int mf = 0; mf < 2; mf++)
                ldsm4(ar[mf], aBase + mf * (16 * 128) + swz[kk]);
            #pragma unroll
            for (int nf = 0; nf < 4; nf++)
                ldsm4(br[nf], bBase + nf * (16 * 128) + swz[kk]);
            #pragma unroll
            for (int mf = 0; mf < 2; mf++)
                #pragma unroll
                for (int ns = 0; ns < 8; ns++)
                    mma_f16(acc[mf][ns], ar[mf],
                            br[ns >> 1][ns & 1], br[ns >> 1][(ns & 1) + 2]);
        }
    }

    // epilogue
    int erow = lane >> 2, ecol = (lane & 3) * 2;
    #pragma unroll
    for (int mf = 0; mf < 2; mf++) {
        int r0 = m0 + wm * 32 + mf * 16 + erow;
        #pragma unroll
        for (int ns = 0; ns < 8; ns++) {
            int cc = n0 + wn * 64 + ns * 8 + ecol;
            float b0 = bias[cc], b1 = bias[cc + 1];
            float v0 = acc[mf][ns][0] + b0;
            float v1 = acc[mf][ns][1] + b1;
            float v2 = acc[mf][ns][2] + b0;
            float v3 = acc[mf][ns][3] + b1;
            if (ACT == 0) {
                *reinterpret_cast<float2*>(&C[(size_t)r0 * N + cc])       = make_float2(v0, v1);
                *reinterpret_cast<float2*>(&C[(size_t)(r0 + 8) * N + cc]) = make_float2(v2, v3);
            } else {
                v0 = 0.5f * v0 * (1.0f + erff(v0 * 0.70710678118654752440f));
                v1 = 0.5f * v1 * (1.0f + erff(v1 * 0.70710678118654752440f));
                v2 = 0.5f * v2 * (1.0f + erff(v2 * 0.70710678118654752440f));
                v3 = 0.5f * v3 * (1.0f + erff(v3 * 0.70710678118654752440f));
                __half* C16 = (__half*)C;
                __half h0 = __float2half(v0), h1 = __float2half(v1);
                __half h2 = __float2half(v2), h3 = __float2half(v3);
                __half l0 = __float2half(v0 - __half2float(h0));
                __half l1 = __float2half(v1 - __half2float(h1));
                __half l2 = __float2half(v2 - __half2float(h2));
                __half l3 = __float2half(v3 - __half2float(h3));
                *reinterpret_cast<__half2*>(&C16[(size_t)r0 * 2 * N + cc])           = __halves2half2(h0, h1);
                *reinterpret_cast<__half2*>(&C16[(size_t)r0 * 2 * N + N + cc])       = __halves2half2(l0, l1);
                *reinterpret_cast<__half2*>(&C16[(size_t)(r0 + 8) * 2 * N + cc])     = __halves2half2(h2, h3);
                *reinterpret_cast<__half2*>(&C16[(size_t)(r0 + 8) * 2 * N + N + cc]) = __halves2half2(l2, l3);
            }
        }
    }
}

// ==================== non-GEMM kernels ====================
__global__ __launch_bounds__(256) void k_embed(
    const int* __restrict__ ids, const float* __restrict__ wemb,
    const float* __restrict__ pemb, const float* __restrict__ lns,
    const float* __restrict__ lnb, float* __restrict__ xout)
{
    __shared__ float red[32];
    int row = blockIdx.x;
    int tid = threadIdx.x;
    int s = row & (SS - 1);
    int id = ids[row];
    const float* we = wemb + (size_t)id * HID;
    const float* pe = pemb + (size_t)s * HID;
    float v0 = we[tid]       + pe[tid];
    float v1 = we[tid + 256] + pe[tid + 256];
    float v2 = we[tid + 512] + pe[tid + 512];
    float mean = blk_sum256(v0 + v1 + v2, red) * (1.0f / HID);
    v0 -= mean; v1 -= mean; v2 -= mean;
    float var = blk_sum256(v0*v0 + v1*v1 + v2*v2, red) * (1.0f / HID);
    float r = rsqrtf(var + 1e-5f);
    size_t base = (size_t)row * HID;
    xout[base + tid]       = v0 * r * lns[tid]       + lnb[tid];
    xout[base + tid + 256] = v1 * r * lns[tid + 256] + lnb[tid + 256];
    xout[base + tid + 512] = v2 * r * lns[tid + 512] + lnb[tid + 512];
}

__global__ __launch_bounds__(256) void k_addln(
    const float* __restrict__ add, const float* __restrict__ lns,
    const float* __restrict__ lnb, float* __restrict__ x)
{
    __shared__ float red[32];
    int row = blockIdx.x;
    int tid = threadIdx.x;
    size_t base = (size_t)row * HID;
    float v0 = x[base + tid]       + add[base + tid];
    float v1 = x[base + tid + 256] + add[base + tid + 256];
    float v2 = x[base + tid + 512] + add[base + tid + 512];
    float mean = blk_sum256(v0 + v1 + v2, red) * (1.0f / HID);
    v0 -= mean; v1 -= mean; v2 -= mean;
    float var = blk_sum256(v0*v0 + v1*v1 + v2*v2, red) * (1.0f / HID);
    float r = rsqrtf(var + 1e-5f);
    x[base + tid]       = v0 * r * lns[tid]       + lnb[tid];
    x[base + tid + 256] = v1 * r * lns[tid + 256] + lnb[tid + 256];
    x[base + tid + 512] = v2 * r * lns[tid + 512] + lnb[tid + 512];
}

__global__ __launch_bounds__(256) void k_qg0(
    const float* __restrict__ x, const float* __restrict__ Wg,
    const float* __restrict__ bg, float* __restrict__ outq)
{
    int b = blockIdx.y;
    int n = blockIdx.x * 256 + threadIdx.x;
    __shared__ float xs[HID];
    for (int i = threadIdx.x; i < HID; i += 256) xs[i] = x[(size_t)b * SS * HID + i];
    __syncthreads();
    float acc = bg[n];
    for (int kk = 0; kk < HID; kk++) acc = fmaf(xs[kk], Wg[(size_t)kk * HID + n], acc);
    outq[b * HID + n] = acc;
}

#define KT 32
__global__ __launch_bounds__(256) void k_band(
    const float* __restrict__ q, const float* __restrict__ k,
    const float* __restrict__ v, const float* __restrict__ kg,
    const float* __restrict__ vg, const int* __restrict__ am,
    float* __restrict__ out)
{
    int c = blockIdx.x, h = blockIdx.y, b = blockIdx.z;
    int p = threadIdx.x;
    int tid = threadIdx.x;
    int qpos = c * WW + p;
    int cstart = (c - 1) * WW;

    __shared__ float4 ks[KT][16];
    __shared__ float4 vs[KT][16];
    __shared__ float kg0[DH], vg0[DH];
    __shared__ unsigned char kval[3 * WW];

    if (tid < DH) {
        kg0[tid] = kg[(size_t)(b * SS) * HID + h * DH + tid];
        vg0[tid] = vg[(size_t)(b * SS) * HID + h * DH + tid];
    }
    for (int j = tid; j < 3 * WW; j += 256) {
        int kp = cstart + j;
        kval[j] = (kp > 0 && kp < SS && am[b * SS + kp] > 0) ? 1 : 0;
    }
    float4 qv[16];
    {
        const float4* qp4 = reinterpret_cast<const float4*>(
            q + (size_t)(b * SS + qpos) * HID + h * DH);
        #pragma unroll
        for (int i = 0; i < 16; i++) qv[i] = qp4[i];
    }
    __syncthreads();

    float m;
    {
        float acc = 0.0f;
        #pragma unroll
        for (int i = 0; i < 16; i++) {
            float4 k4 = reinterpret_cast<const float4*>(kg0)[i];
            acc += qv[i].x * k4.x + qv[i].y * k4.y + qv[i].z * k4.z + qv[i].w * k4.w;
        }
        m = acc * 0.125f;
    }
    float l = 1.0f;
    float4 accv[16];
    #pragma unroll
    for (int i = 0; i < 16; i++) accv[i] = reinterpret_cast<const float4*>(vg0)[i];

    for (int kt0 = 0; kt0 < 3 * WW; kt0 += KT) {
        __syncthreads();
        for (int t = tid; t < KT * 16; t += 256) {
            int jj = t >> 4, dd = t & 15;
            int kp = cstart + kt0 + jj;
            float4 kv4 = make_float4(0, 0, 0, 0), vv4 = make_float4(0, 0, 0, 0);
            if (kp >= 0 && kp < SS) {
                size_t base = (size_t)(b * SS + kp) * HID + h * DH;
                kv4 = *reinterpret_cast<const float4*>(k + base + dd * 4);
                vv4 = *reinterpret_cast<const float4*>(v + base + dd * 4);
            }
            ks[jj][dd] = kv4;
            vs[jj][dd] = vv4;
        }
        __syncthreads();
        int jlo = max(p - kt0, 0);
        int jhi = min(p + 2 * WW - kt0, KT - 1);
        for (int jj = jlo; jj <= jhi; jj++) {
            int j = kt0 + jj;
            if (!kval[j]) continue;
            float acc = 0.0f;
            #pragma unroll
            for (int i = 0; i < 16; i++) {
                float4 k4 = ks[jj][i];
                acc += qv[i].x * k4.x + qv[i].y * k4.y + qv[i].z * k4.z + qv[i].w * k4.w;
            }
            float sscore = acc * 0.125f;
            float mnew = fmaxf(m, sscore);
            float fac = __expf(m - mnew);
            float wgt = __expf(sscore - mnew);
            l = l * fac + wgt;
            #pragma unroll
            for (int i = 0; i < 16; i++) {
                float4 vv4 = vs[jj][i];
                accv[i].x = accv[i].x * fac + wgt * vv4.x;
                accv[i].y = accv[i].y * fac + wgt * vv4.y;
                accv[i].z = accv[i].z * fac + wgt * vv4.z;
                accv[i].w = accv[i].w * fac + wgt * vv4.w;
            }
            m = mnew;
        }
    }
    float inv = 1.0f / l;
    float4* op4 = reinterpret_cast<float4*>(out + (size_t)(b * SS + qpos) * HID + h * DH);
    #pragma unroll
    for (int i = 0; i < 16; i++) {
        accv[i].x *= inv; accv[i].y *= inv; accv[i].z *= inv; accv[i].w *= inv;
        op4[i] = accv[i];
    }
}

__global__ __launch_bounds__(256) void k_glob(
    const float* __restrict__ qg0, const float* __restrict__ kg,
    const float* __restrict__ vg, const int* __restrict__ am,
    float* __restrict__ out)
{
    int b = blockIdx.x / HEADS;
    int h = blockIdx.x % HEADS;
    int tid = threadIdx.x;
    __shared__ float sc[SS];
    __shared__ float q0[DH];
    __shared__ float red[32];
    __shared__ float part[4][DH];

    if (tid < DH) q0[tid] = qg0[b * HID + h * DH + tid];
    __syncthreads();

    float lmax = -3.0e38f;
    for (int j = tid; j < SS; j += 256) {
        float sv = -1e9f;
        if (am[b * SS + j] > 0) {
            const float4* kr = reinterpret_cast<const float4*>(
                kg + (size_t)(b * SS + j) * HID + h * DH);
            float acc = 0.0f;
            #pragma unroll
            for (int i = 0; i < 16; i++) {
                float4 k4 = kr[i];
                float4 q4 = reinterpret_cast<const float4*>(q0)[i];
                acc += q4.x * k4.x + q4.y * k4.y + q4.z * k4.z + q4.w * k4.w;
            }
            sv = acc * 0.125f;
        }
        sc[j] = sv;
        lmax = fmaxf(lmax, sv);
    }
    float mm = blk_max256(lmax, red);
    float ls = 0.0f;
    for (int j = tid; j < SS; j += 256) {
        float w = __expf(sc[j] - mm);
        sc[j] = w;
        ls += w;
    }
    float sum = blk_sum256(ls, red);
    __syncthreads();

    int d = tid & 63, g = tid >> 6;
    float acc = 0.0f;
    for (int j = g; j < SS; j += 4)
        acc = fmaf(sc[j], vg[(size_t)(b * SS + j) * HID + h * DH + d], acc);
    part[g][d] = acc;
    __syncthreads();
    if (tid < DH) {
        float o = (part[0][tid] + part[1][tid] + part[2][tid] + part[3][tid]) / sum;
        out[(size_t)(b * SS) * HID + h * DH + tid] = o;
    }
}

__global__ __launch_bounds__(128) void k_head(
    const float* __restrict__ x, const float* __restrict__ hw,
    const float* __restrict__ hb, float* __restrict__ out)
{
    int b = blockIdx.y;
    int n = blockIdx.x * 128 + threadIdx.x;
    __shared__ float xs[HID];
    for (int i = threadIdx.x; i < HID; i += 128) xs[i] = x[(size_t)b * SS * HID + i];
    __syncthreads();
    if (n >= NLAB) return;
    float acc = hb[n];
    for (int kk = 0; kk < HID; kk++) acc = fmaf(xs[kk], hw[(size_t)kk * NLAB + n], acc);
    out[b * NLAB + n] = acc;
}

// ==================== orchestration ====================
extern "C" void kernel_launch(void* const* d_in, const int* in_sizes, int n_in,
                              void* d_out, int out_size)
{
    const int*   ids  = (const int*)d_in[0];
    const int*   am   = (const int*)d_in[1];
    const float* wemb = (const float*)d_in[2];
    const float* pemb = (const float*)d_in[3];
    const float* elns = (const float*)d_in[4];
    const float* elnb = (const float*)d_in[5];
    const float* Wq   = (const float*)d_in[6];
    const float* bq   = (const float*)d_in[7];
    const float* Wk   = (const float*)d_in[8];
    const float* bk   = (const float*)d_in[9];
    const float* Wv   = (const float*)d_in[10];
    const float* bv   = (const float*)d_in[11];
    const float* Wqg  = (const float*)d_in[12];
    const float* bqg  = (const float*)d_in[13];
    const float* Wkg  = (const float*)d_in[14];
    const float* bkg  = (const float*)d_in[15];
    const float* Wvg  = (const float*)d_in[16];
    const float* bvg  = (const float*)d_in[17];
    const float* Wo   = (const float*)d_in[18];
    const float* bo   = (const float*)d_in[19];
    const float* ln1s = (const float*)d_in[20];
    const float* ln1b = (const float*)d_in[21];
    const float* W1   = (const float*)d_in[22];
    const float* b1   = (const float*)d_in[23];
    const float* W2   = (const float*)d_in[24];
    const float* b2   = (const float*)d_in[25];
    const float* ln2s = (const float*)d_in[26];
    const float* ln2b = (const float*)d_in[27];
    const float* hW   = (const float*)d_in[28];
    const float* hb   = (const float*)d_in[29];
    float* out = (float*)d_out;

    float *px, *pq, *pk, *pv, *pkg, *pvg, *pattn, *ptmp, *pqg0;
    __half *pwt, *pw1t, *pw2t, *pab, *pab2;
    cudaGetSymbolAddress((void**)&px,   g_x);
    cudaGetSymbolAddress((void**)&pq,   g_q);
    cudaGetSymbolAddress((void**)&pk,   g_k);
    cudaGetSymbolAddress((void**)&pv,   g_v);
    cudaGetSymbolAddress((void**)&pkg,  g_kg);
    cudaGetSymbolAddress((void**)&pvg,  g_vg);
    cudaGetSymbolAddress((void**)&pattn,g_attn);
    cudaGetSymbolAddress((void**)&ptmp, g_tmp);
    cudaGetSymbolAddress((void**)&pqg0, g_qg0);
    cudaGetSymbolAddress((void**)&pwt,  g_wt);
    cudaGetSymbolAddress((void**)&pw1t, g_w1t);
    cudaGetSymbolAddress((void**)&pw2t, g_w2t);
    cudaGetSymbolAddress((void**)&pab,  g_ab);
    cudaGetSymbolAddress((void**)&pab2, g_ab2);

    cudaFuncSetAttribute(k_wmma<0>, cudaFuncAttributeMaxDynamicSharedMemorySize, MM_SMEM);
    cudaFuncSetAttribute(k_wmma<1>, cudaFuncAttributeMaxDynamicSharedMemorySize, MM_SMEM);

    const size_t WSTRIDE = (size_t)HID * HID;   // one converted weight matrix (fp16)

    // ---- weight conversions ----
    for (int l = 0; l < 2; l++) {
        size_t ow  = (size_t)l * HID * HID;
        size_t ow1 = (size_t)l * HID * FFNDIM;
        const float* Ws[6] = {Wq + ow, Wk + ow, Wv + ow, Wkg + ow, Wvg + ow, Wo + ow};
        for (int i = 0; i < 6; i++)
            k_cvtw<<<dim3(HID / 32, HID / 32), 256>>>(Ws[i], pwt + (size_t)(l * 6 + i) * WSTRIDE, HID, HID);
        k_cvtw<<<dim3(HID / 32, FFNDIM / 32), 256>>>(W1 + ow1, pw1t + (size_t)l * FFNDIM * HID, HID, FFNDIM);
        k_cvtw<<<dim3(FFNDIM / 32, HID / 32), 256>>>(W2 + ow1, pw2t + (size_t)l * HID * FFNDIM, FFNDIM, HID);
    }

    k_embed<<<NTOK, 256>>>(ids, wemb, pemb, elns, elnb, px);

    const int CVT_H = NTOK * (HID / 4) / 256;     // 6144

    for (int l = 0; l < 2; l++) {
        size_t ow  = (size_t)l * HID * HID;
        size_t ob  = (size_t)l * HID;
        size_t ob1 = (size_t)l * FFNDIM;
        const __half* wl = pwt + (size_t)(l * 6) * WSTRIDE;

        // x -> split; 5 projections batched
        k_cvta<<<CVT_H, 256>>>(px, pab2, HID);
        {
            TcB b5;
            b5.W[0] = wl + 0 * WSTRIDE; b5.b[0] = bq  + ob; b5.C[0] = pq;
            b5.W[1] = wl + 1 * WSTRIDE; b5.b[1] = bk  + ob; b5.C[1] = pk;
            b5.W[2] = wl + 2 * WSTRIDE; b5.b[2] = bv  + ob; b5.C[2] = pv;
            b5.W[3] = wl + 3 * WSTRIDE; b5.b[3] = bkg + ob; b5.C[3] = pkg;
            b5.W[4] = wl + 4 * WSTRIDE; b5.b[4] = bvg + ob; b5.C[4] = pvg;
            k_wmma<0><<<dim3(HID / 128, NTOK / 128, 5), 256, MM_SMEM>>>(pab2, b5, HID, HID);
        }
        k_qg0<<<dim3(3, BB), 256>>>(px, Wqg + ow, bqg + ob, pqg0);

        k_band<<<dim3(NC, HEADS, BB), 256>>>(pq, pk, pv, pkg, pvg, am, pattn);
        k_glob<<<BB * HEADS, 256>>>(pqg0, pkg, pvg, am, pattn);

        // attn @ Wo
        k_cvta<<<CVT_H, 256>>>(pattn, pab2, HID);
        {
            TcB bo5; bo5.W[0] = wl + 5 * WSTRIDE; bo5.b[0] = bo + ob; bo5.C[0] = ptmp;
            k_wmma<0><<<dim3(HID / 128, NTOK / 128, 1), 256, MM_SMEM>>>(pab2, bo5, HID, HID);
        }
        k_addln<<<NTOK, 256>>>(ptmp, ln1s + ob, ln1b + ob, px);

        // FFN: W1 writes GELU'd split fp16 directly into pab (stride 2*FFNDIM)
        k_cvta<<<CVT_H, 256>>>(px, pab2, HID);
        {
            TcB bw1; bw1.W[0] = pw1t + (size_t)l * FFNDIM * HID; bw1.b[0] = b1 + ob1;
            bw1.C[0] = (float*)pab;
            k_wmma<1><<<dim3(FFNDIM / 128, NTOK / 128, 1), 256, MM_SMEM>>>(pab2, bw1, FFNDIM, HID);
        }
        {
            TcB bw2; bw2.W[0] = pw2t + (size_t)l * HID * FFNDIM; bw2.b[0] = b2 + ob; bw2.C[0] = ptmp;
            k_wmma<0><<<dim3(HID / 128, NTOK / 128, 1), 256, MM_SMEM>>>(pab, bw2, HID, FFNDIM);
        }
        k_addln<<<NTOK, 256>>>(ptmp, ln2s + ob, ln2b + ob, px);
    }

    k_head<<<dim3((NLAB + 127) / 128, BB), 128>>>(px, hW, hb, out);
}

// round 7
// speedup vs baseline: 2.3282x; 1.3289x over previous
#include <cuda_runtime.h>
#include <cuda_fp16.h>
#include <math.h>
#include <stdint.h>

#define HID 768
#define HEADS 12
#define DH 64
#define WW 256
#define NC 16
#define FFNDIM 3072
#define NLAB 8921
#define BB 2
#define SS 4096
#define NTOK (BB*SS)

// -------- scratch (device globals; no allocation allowed) --------
__device__ __align__(256) float g_x[NTOK*HID];
__device__ __align__(256) float g_q[NTOK*HID];
__device__ __align__(256) float g_k[NTOK*HID];
__device__ __align__(256) float g_v[NTOK*HID];
__device__ __align__(256) float g_kg[NTOK*HID];
__device__ __align__(256) float g_vg[NTOK*HID];
__device__ __align__(256) float g_attn[NTOK*HID];
__device__ __align__(256) float g_tmp[NTOK*HID];
__device__ __align__(256) float g_qg0[BB*HID];
// fp16 operands: weights single-rounded (transposed), activations single-rounded
__device__ __align__(256) __half g_wt[(size_t)2*6*HID*HID];
__device__ __align__(256) __half g_w1t[(size_t)2*FFNDIM*HID];
__device__ __align__(256) __half g_w2t[(size_t)2*HID*FFNDIM];
__device__ __align__(256) __half g_ab[(size_t)NTOK*FFNDIM];   // FFN intermediate fp16
__device__ __align__(256) __half g_ab2[(size_t)NTOK*HID];     // HID-wide fp16 activations

// ==================== small helpers ====================
__device__ __forceinline__ uint32_t s2u(const void* p) {
    uint32_t a;
    asm("{ .reg .u64 t; cvta.to.shared.u64 t, %1; cvt.u32.u64 %0, t; }" : "=r"(a) : "l"(p));
    return a;
}
__device__ __forceinline__ void cp16(uint32_t s, const void* g) {
    asm volatile("cp.async.cg.shared.global [%0], [%1], 16;" :: "r"(s), "l"(g));
}
__device__ __forceinline__ void ldsm4(uint32_t* r, uint32_t addr) {
    asm volatile("ldmatrix.sync.aligned.m8n8.x4.shared.b16 {%0,%1,%2,%3}, [%4];"
        : "=r"(r[0]), "=r"(r[1]), "=r"(r[2]), "=r"(r[3]) : "r"(addr));
}
__device__ __forceinline__ void mma_f16(float* d, const uint32_t* a, uint32_t b0, uint32_t b1) {
    asm volatile(
        "mma.sync.aligned.m16n8k16.row.col.f32.f16.f16.f32 "
        "{%0,%1,%2,%3}, {%4,%5,%6,%7}, {%8,%9}, {%0,%1,%2,%3};"
        : "+f"(d[0]), "+f"(d[1]), "+f"(d[2]), "+f"(d[3])
        : "r"(a[0]), "r"(a[1]), "r"(a[2]), "r"(a[3]), "r"(b0), "r"(b1));
}

// -------- block reduction helpers (256 threads) --------
__device__ __forceinline__ float blk_sum256(float v, float* red) {
    #pragma unroll
    for (int o = 16; o > 0; o >>= 1) v += __shfl_xor_sync(0xffffffffu, v, o);
    int w = threadIdx.x >> 5, ln = threadIdx.x & 31;
    if (ln == 0) red[w] = v;
    __syncthreads();
    if (w == 0) {
        float t = (ln < 8) ? red[ln] : 0.0f;
        #pragma unroll
        for (int o = 4; o > 0; o >>= 1) t += __shfl_xor_sync(0xffffffffu, t, o);
        if (ln == 0) red[0] = t;
    }
    __syncthreads();
    float r = red[0];
    __syncthreads();
    return r;
}
__device__ __forceinline__ float blk_max256(float v, float* red) {
    #pragma unroll
    for (int o = 16; o > 0; o >>= 1) v = fmaxf(v, __shfl_xor_sync(0xffffffffu, v, o));
    int w = threadIdx.x >> 5, ln = threadIdx.x & 31;
    if (ln == 0) red[w] = v;
    __syncthreads();
    if (w == 0) {
        float t = (ln < 8) ? red[ln] : -3.0e38f;
        #pragma unroll
        for (int o = 4; o > 0; o >>= 1) t = fmaxf(t, __shfl_xor_sync(0xffffffffu, t, o));
        if (ln == 0) red[0] = t;
    }
    __syncthreads();
    float r = red[0];
    __syncthreads();
    return r;
}

// ==================== conversion kernels ====================
// W[K,N] fp32 -> O[N,K] fp16 transposed (single rounding)
__global__ __launch_bounds__(256) void k_cvtw(
    const float* __restrict__ W, __half* __restrict__ O, int K, int N)
{
    __shared__ float tile[32][33];
    int k0 = blockIdx.x * 32, n0 = blockIdx.y * 32;
    int tx = threadIdx.x & 31, ty = threadIdx.x >> 5;
    #pragma unroll
    for (int j = 0; j < 32; j += 8)
        tile[ty + j][tx] = W[(size_t)(k0 + ty + j) * N + n0 + tx];
    __syncthreads();
    #pragma unroll
    for (int j = 0; j < 32; j += 8) {
        int n = n0 + ty + j, k = k0 + tx;
        O[(size_t)n * K + k] = __float2half(tile[tx][ty + j]);
    }
}

// A (fp32, contiguous) -> O fp16 (single rounding); thread = 4 elements
__global__ __launch_bounds__(256) void k_cvta(
    const float* __restrict__ A, __half* __restrict__ O)
{
    int idx = blockIdx.x * 256 + threadIdx.x;
    float4 a = reinterpret_cast<const float4*>(A)[idx];
    __half h[4];
    h[0] = __float2half(a.x); h[1] = __float2half(a.y);
    h[2] = __float2half(a.z); h[3] = __float2half(a.w);
    *reinterpret_cast<uint2*>(O + 4 * (size_t)idx) = *reinterpret_cast<uint2*>(h);
}

// ==================== fp16 mma.sync GEMM ====================
// C = A.B^T + bias. A fp16 stride K; B fp16 stride K (pre-transposed).
// ACT 0: fp32 out. ACT 1: GELU then write plain fp16 stride N.
struct TcB {
    const __half* W[5];
    const float* b[5];
    float* C[5];
};

#define STG_BYTES 32768                // A 16KB + B 16KB per stage
#define MM_STG 3
#define MM_SMEM (MM_STG*STG_BYTES)     // 96KB

template <int ACT>
__global__ __launch_bounds__(256, 2) void k_wmma(
    const __half* __restrict__ A, TcB bt, int N, int K)
{
    extern __shared__ char smem[];
    const int z = blockIdx.z;
    const __half* Bw = bt.W[z];
    const float* bias = bt.b[z];
    float* C = bt.C[z];
    const int m0 = blockIdx.y * 128, n0 = blockIdx.x * 128;
    int tid = threadIdx.x, lane = tid & 31, wid = tid >> 5;
    int wm = wid & 3, wn = wid >> 2;
    uint32_t sb = s2u(smem);

    const int NIT = K >> 6;           // 64-elem chunks

    // ---- cp.async mapping: row = tid&127, 4 chunks of 16B per matrix ----
    int lr = tid & 127;
    int half_ = tid >> 7;             // 0/1 -> chunks 0-3 / 4-7
    const char* gAr = (const char*)(A + (size_t)(m0 + lr) * K);
    const char* gBr = (const char*)(Bw + (size_t)(n0 + lr) * K);
    uint32_t stoff[4];
    uint32_t gcol[4];
    #pragma unroll
    for (int j = 0; j < 4; j++) {
        int c16 = half_ * 4 + j;
        stoff[j] = (uint32_t)(lr * 128 + ((c16 ^ (lr & 7)) << 4));
        gcol[j] = (uint32_t)(c16 << 4);
    }

    float acc[2][8][4];
    #pragma unroll
    for (int i = 0; i < 2; i++)
        #pragma unroll
        for (int j = 0; j < 8; j++)
            #pragma unroll
            for (int c = 0; c < 4; c++) acc[i][j][c] = 0.0f;

    auto issue = [&](int t) {
        int b = t % MM_STG;
        uint32_t base = sb + b * STG_BYTES;
        size_t off = (size_t)t * 128;  // bytes along K
        #pragma unroll
        for (int j = 0; j < 4; j++) cp16(base + stoff[j], gAr + off + gcol[j]);
        #pragma unroll
        for (int j = 0; j < 4; j++) cp16(base + 16384 + stoff[j], gBr + off + gcol[j]);
        asm volatile("cp.async.commit_group;" ::: "memory");
    };
    issue(0); issue(1);

    // ---- ldmatrix addressing (swizzled) ----
    int lrow = lane & 15, lk8 = lane >> 4, rxor = lrow & 7;
    uint32_t aRow = (uint32_t)((wm * 32 + lrow) * 128);
    uint32_t bRow = (uint32_t)((wn * 64 + lrow) * 128);
    uint32_t swz[4];
    #pragma unroll
    for (int kk = 0; kk < 4; kk++)
        swz[kk] = (uint32_t)((((kk * 2) + lk8) ^ rxor) << 4);

    for (int t = 0; t < NIT; t++) {
        if (t == NIT - 1) asm volatile("cp.async.wait_group 0;" ::: "memory");
        else              asm volatile("cp.async.wait_group 1;" ::: "memory");
        __syncthreads();
        if (t + 2 < NIT) issue(t + 2);

        int b = t % MM_STG;
        uint32_t aBase = sb + b * STG_BYTES + aRow;
        uint32_t bBase = sb + b * STG_BYTES + 16384 + bRow;
        #pragma unroll
        for (int kk = 0; kk < 4; kk++) {
            uint32_t ar[2][4], br[4][4];
            #pragma unroll
            for (int mf = 0; mf < 2; mf++)
                ldsm4(ar[mf], aBase + mf * (16 * 128) + swz[kk]);
            #pragma unroll
            for (int nf = 0; nf < 4; nf++)
                ldsm4(br[nf], bBase + nf * (16 * 128) + swz[kk]);
            #pragma unroll
            for (int mf = 0; mf < 2; mf++)
                #pragma unroll
                for (int ns = 0; ns < 8; ns++)
                    mma_f16(acc[mf][ns], ar[mf],
                            br[ns >> 1][ns & 1], br[ns >> 1][(ns & 1) + 2]);
        }
    }

    // epilogue
    int erow = lane >> 2, ecol = (lane & 3) * 2;
    #pragma unroll
    for (int mf = 0; mf < 2; mf++) {
        int r0 = m0 + wm * 32 + mf * 16 + erow;
        #pragma unroll
        for (int ns = 0; ns < 8; ns++) {
            int cc = n0 + wn * 64 + ns * 8 + ecol;
            float b0 = bias[cc], b1 = bias[cc + 1];
            float v0 = acc[mf][ns][0] + b0;
            float v1 = acc[mf][ns][1] + b1;
            float v2 = acc[mf][ns][2] + b0;
            float v3 = acc[mf][ns][3] + b1;
            if (ACT == 0) {
                *reinterpret_cast<float2*>(&C[(size_t)r0 * N + cc])       = make_float2(v0, v1);
                *reinterpret_cast<float2*>(&C[(size_t)(r0 + 8) * N + cc]) = make_float2(v2, v3);
            } else {
                v0 = 0.5f * v0 * (1.0f + erff(v0 * 0.70710678118654752440f));
                v1 = 0.5f * v1 * (1.0f + erff(v1 * 0.70710678118654752440f));
                v2 = 0.5f * v2 * (1.0f + erff(v2 * 0.70710678118654752440f));
                v3 = 0.5f * v3 * (1.0f + erff(v3 * 0.70710678118654752440f));
                __half* C16 = (__half*)C;
                *reinterpret_cast<__half2*>(&C16[(size_t)r0 * N + cc]) =
                    __halves2half2(__float2half(v0), __float2half(v1));
                *reinterpret_cast<__half2*>(&C16[(size_t)(r0 + 8) * N + cc]) =
                    __halves2half2(__float2half(v2), __float2half(v3));
            }
        }
    }
}

// ==================== non-GEMM kernels ====================
__global__ __launch_bounds__(256) void k_embed(
    const int* __restrict__ ids, const float* __restrict__ wemb,
    const float* __restrict__ pemb, const float* __restrict__ lns,
    const float* __restrict__ lnb, float* __restrict__ xout)
{
    __shared__ float red[32];
    int row = blockIdx.x;
    int tid = threadIdx.x;
    int s = row & (SS - 1);
    int id = ids[row];
    const float* we = wemb + (size_t)id * HID;
    const float* pe = pemb + (size_t)s * HID;
    float v0 = we[tid]       + pe[tid];
    float v1 = we[tid + 256] + pe[tid + 256];
    float v2 = we[tid + 512] + pe[tid + 512];
    float mean = blk_sum256(v0 + v1 + v2, red) * (1.0f / HID);
    v0 -= mean; v1 -= mean; v2 -= mean;
    float var = blk_sum256(v0*v0 + v1*v1 + v2*v2, red) * (1.0f / HID);
    float r = rsqrtf(var + 1e-5f);
    size_t base = (size_t)row * HID;
    xout[base + tid]       = v0 * r * lns[tid]       + lnb[tid];
    xout[base + tid + 256] = v1 * r * lns[tid + 256] + lnb[tid + 256];
    xout[base + tid + 512] = v2 * r * lns[tid + 512] + lnb[tid + 512];
}

__global__ __launch_bounds__(256) void k_addln(
    const float* __restrict__ add, const float* __restrict__ lns,
    const float* __restrict__ lnb, float* __restrict__ x)
{
    __shared__ float red[32];
    int row = blockIdx.x;
    int tid = threadIdx.x;
    size_t base = (size_t)row * HID;
    float v0 = x[base + tid]       + add[base + tid];
    float v1 = x[base + tid + 256] + add[base + tid + 256];
    float v2 = x[base + tid + 512] + add[base + tid + 512];
    float mean = blk_sum256(v0 + v1 + v2, red) * (1.0f / HID);
    v0 -= mean; v1 -= mean; v2 -= mean;
    float var = blk_sum256(v0*v0 + v1*v1 + v2*v2, red) * (1.0f / HID);
    float r = rsqrtf(var + 1e-5f);
    x[base + tid]       = v0 * r * lns[tid]       + lnb[tid];
    x[base + tid + 256] = v1 * r * lns[tid + 256] + lnb[tid + 256];
    x[base + tid + 512] = v2 * r * lns[tid + 512] + lnb[tid + 512];
}

__global__ __launch_bounds__(256) void k_qg0(
    const float* __restrict__ x, const float* __restrict__ Wg,
    const float* __restrict__ bg, float* __restrict__ outq)
{
    int b = blockIdx.y;
    int n = blockIdx.x * 256 + threadIdx.x;
    __shared__ float xs[HID];
    for (int i = threadIdx.x; i < HID; i += 256) xs[i] = x[(size_t)b * SS * HID + i];
    __syncthreads();
    float acc = bg[n];
    for (int kk = 0; kk < HID; kk++) acc = fmaf(xs[kk], Wg[(size_t)kk * HID + n], acc);
    outq[b * HID + n] = acc;
}

#define KT 32
__global__ __launch_bounds__(256) void k_band(
    const float* __restrict__ q, const float* __restrict__ k,
    const float* __restrict__ v, const float* __restrict__ kg,
    const float* __restrict__ vg, const int* __restrict__ am,
    float* __restrict__ out)
{
    int c = blockIdx.x, h = blockIdx.y, b = blockIdx.z;
    int p = threadIdx.x;
    int tid = threadIdx.x;
    int qpos = c * WW + p;
    int cstart = (c - 1) * WW;

    __shared__ float4 ks[KT][16];
    __shared__ float4 vs[KT][16];
    __shared__ float kg0[DH], vg0[DH];
    __shared__ unsigned char kval[3 * WW];

    if (tid < DH) {
        kg0[tid] = kg[(size_t)(b * SS) * HID + h * DH + tid];
        vg0[tid] = vg[(size_t)(b * SS) * HID + h * DH + tid];
    }
    for (int j = tid; j < 3 * WW; j += 256) {
        int kp = cstart + j;
        kval[j] = (kp > 0 && kp < SS && am[b * SS + kp] > 0) ? 1 : 0;
    }
    float4 qv[16];
    {
        const float4* qp4 = reinterpret_cast<const float4*>(
            q + (size_t)(b * SS + qpos) * HID + h * DH);
        #pragma unroll
        for (int i = 0; i < 16; i++) qv[i] = qp4[i];
    }
    __syncthreads();

    float m;
    {
        float acc = 0.0f;
        #pragma unroll
        for (int i = 0; i < 16; i++) {
            float4 k4 = reinterpret_cast<const float4*>(kg0)[i];
            acc += qv[i].x * k4.x + qv[i].y * k4.y + qv[i].z * k4.z + qv[i].w * k4.w;
        }
        m = acc * 0.125f;
    }
    float l = 1.0f;
    float4 accv[16];
    #pragma unroll
    for (int i = 0; i < 16; i++) accv[i] = reinterpret_cast<const float4*>(vg0)[i];

    for (int kt0 = 0; kt0 < 3 * WW; kt0 += KT) {
        __syncthreads();
        for (int t = tid; t < KT * 16; t += 256) {
            int jj = t >> 4, dd = t & 15;
            int kp = cstart + kt0 + jj;
            float4 kv4 = make_float4(0, 0, 0, 0), vv4 = make_float4(0, 0, 0, 0);
            if (kp >= 0 && kp < SS) {
                size_t base = (size_t)(b * SS + kp) * HID + h * DH;
                kv4 = *reinterpret_cast<const float4*>(k + base + dd * 4);
                vv4 = *reinterpret_cast<const float4*>(v + base + dd * 4);
            }
            ks[jj][dd] = kv4;
            vs[jj][dd] = vv4;
        }
        __syncthreads();
        int jlo = max(p - kt0, 0);
        int jhi = min(p + 2 * WW - kt0, KT - 1);
        for (int jj = jlo; jj <= jhi; jj++) {
            int j = kt0 + jj;
            if (!kval[j]) continue;
            float acc = 0.0f;
            #pragma unroll
            for (int i = 0; i < 16; i++) {
                float4 k4 = ks[jj][i];
                acc += qv[i].x * k4.x + qv[i].y * k4.y + qv[i].z * k4.z + qv[i].w * k4.w;
            }
            float sscore = acc * 0.125f;
            float mnew = fmaxf(m, sscore);
            float fac = __expf(m - mnew);
            float wgt = __expf(sscore - mnew);
            l = l * fac + wgt;
            #pragma unroll
            for (int i = 0; i < 16; i++) {
                float4 vv4 = vs[jj][i];
                accv[i].x = accv[i].x * fac + wgt * vv4.x;
                accv[i].y = accv[i].y * fac + wgt * vv4.y;
                accv[i].z = accv[i].z * fac + wgt * vv4.z;
                accv[i].w = accv[i].w * fac + wgt * vv4.w;
            }
            m = mnew;
        }
    }
    float inv = 1.0f / l;
    float4* op4 = reinterpret_cast<float4*>(out + (size_t)(b * SS + qpos) * HID + h * DH);
    #pragma unroll
    for (int i = 0; i < 16; i++) {
        accv[i].x *= inv; accv[i].y *= inv; accv[i].z *= inv; accv[i].w *= inv;
        op4[i] = accv[i];
    }
}

__global__ __launch_bounds__(256) void k_glob(
    const float* __restrict__ qg0, const float* __restrict__ kg,
    const float* __restrict__ vg, const int* __restrict__ am,
    float* __restrict__ out)
{
    int b = blockIdx.x / HEADS;
    int h = blockIdx.x % HEADS;
    int tid = threadIdx.x;
    __shared__ float sc[SS];
    __shared__ float q0[DH];
    __shared__ float red[32];
    __shared__ float part[4][DH];

    if (tid < DH) q0[tid] = qg0[b * HID + h * DH + tid];
    __syncthreads();

    float lmax = -3.0e38f;
    for (int j = tid; j < SS; j += 256) {
        float sv = -1e9f;
        if (am[b * SS + j] > 0) {
            const float4* kr = reinterpret_cast<const float4*>(
                kg + (size_t)(b * SS + j) * HID + h * DH);
            float acc = 0.0f;
            #pragma unroll
            for (int i = 0; i < 16; i++) {
                float4 k4 = kr[i];
                float4 q4 = reinterpret_cast<const float4*>(q0)[i];
                acc += q4.x * k4.x + q4.y * k4.y + q4.z * k4.z + q4.w * k4.w;
            }
            sv = acc * 0.125f;
        }
        sc[j] = sv;
        lmax = fmaxf(lmax, sv);
    }
    float mm = blk_max256(lmax, red);
    float ls = 0.0f;
    for (int j = tid; j < SS; j += 256) {
        float w = __expf(sc[j] - mm);
        sc[j] = w;
        ls += w;
    }
    float sum = blk_sum256(ls, red);
    __syncthreads();

    int d = tid & 63, g = tid >> 6;
    float acc = 0.0f;
    for (int j = g; j < SS; j += 4)
        acc = fmaf(sc[j], vg[(size_t)(b * SS + j) * HID + h * DH + d], acc);
    part[g][d] = acc;
    __syncthreads();
    if (tid < DH) {
        float o = (part[0][tid] + part[1][tid] + part[2][tid] + part[3][tid]) / sum;
        out[(size_t)(b * SS) * HID + h * DH + tid] = o;
    }
}

__global__ __launch_bounds__(128) void k_head(
    const float* __restrict__ x, const float* __restrict__ hw,
    const float* __restrict__ hb, float* __restrict__ out)
{
    int b = blockIdx.y;
    int n = blockIdx.x * 128 + threadIdx.x;
    __shared__ float xs[HID];
    for (int i = threadIdx.x; i < HID; i += 128) xs[i] = x[(size_t)b * SS * HID + i];
    __syncthreads();
    if (n >= NLAB) return;
    float acc = hb[n];
    for (int kk = 0; kk < HID; kk++) acc = fmaf(xs[kk], hw[(size_t)kk * NLAB + n], acc);
    out[b * NLAB + n] = acc;
}

// ==================== orchestration ====================
extern "C" void kernel_launch(void* const* d_in, const int* in_sizes, int n_in,
                              void* d_out, int out_size)
{
    const int*   ids  = (const int*)d_in[0];
    const int*   am   = (const int*)d_in[1];
    const float* wemb = (const float*)d_in[2];
    const float* pemb = (const float*)d_in[3];
    const float* elns = (const float*)d_in[4];
    const float* elnb = (const float*)d_in[5];
    const float* Wq   = (const float*)d_in[6];
    const float* bq   = (const float*)d_in[7];
    const float* Wk   = (const float*)d_in[8];
    const float* bk   = (const float*)d_in[9];
    const float* Wv   = (const float*)d_in[10];
    const float* bv   = (const float*)d_in[11];
    const float* Wqg  = (const float*)d_in[12];
    const float* bqg  = (const float*)d_in[13];
    const float* Wkg  = (const float*)d_in[14];
    const float* bkg  = (const float*)d_in[15];
    const float* Wvg  = (const float*)d_in[16];
    const float* bvg  = (const float*)d_in[17];
    const float* Wo   = (const float*)d_in[18];
    const float* bo   = (const float*)d_in[19];
    const float* ln1s = (const float*)d_in[20];
    const float* ln1b = (const float*)d_in[21];
    const float* W1   = (const float*)d_in[22];
    const float* b1   = (const float*)d_in[23];
    const float* W2   = (const float*)d_in[24];
    const float* b2   = (const float*)d_in[25];
    const float* ln2s = (const float*)d_in[26];
    const float* ln2b = (const float*)d_in[27];
    const float* hW   = (const float*)d_in[28];
    const float* hb   = (const float*)d_in[29];
    float* out = (float*)d_out;

    float *px, *pq, *pk, *pv, *pkg, *pvg, *pattn, *ptmp, *pqg0;
    __half *pwt, *pw1t, *pw2t, *pab, *pab2;
    cudaGetSymbolAddress((void**)&px,   g_x);
    cudaGetSymbolAddress((void**)&pq,   g_q);
    cudaGetSymbolAddress((void**)&pk,   g_k);
    cudaGetSymbolAddress((void**)&pv,   g_v);
    cudaGetSymbolAddress((void**)&pkg,  g_kg);
    cudaGetSymbolAddress((void**)&pvg,  g_vg);
    cudaGetSymbolAddress((void**)&pattn,g_attn);
    cudaGetSymbolAddress((void**)&ptmp, g_tmp);
    cudaGetSymbolAddress((void**)&pqg0, g_qg0);
    cudaGetSymbolAddress((void**)&pwt,  g_wt);
    cudaGetSymbolAddress((void**)&pw1t, g_w1t);
    cudaGetSymbolAddress((void**)&pw2t, g_w2t);
    cudaGetSymbolAddress((void**)&pab,  g_ab);
    cudaGetSymbolAddress((void**)&pab2, g_ab2);

    cudaFuncSetAttribute(k_wmma<0>, cudaFuncAttributeMaxDynamicSharedMemorySize, MM_SMEM);
    cudaFuncSetAttribute(k_wmma<1>, cudaFuncAttributeMaxDynamicSharedMemorySize, MM_SMEM);

    const size_t WSTRIDE = (size_t)HID * HID;   // one converted weight matrix (fp16)

    // ---- weight conversions ----
    for (int l = 0; l < 2; l++) {
        size_t ow  = (size_t)l * HID * HID;
        size_t ow1 = (size_t)l * HID * FFNDIM;
        const float* Ws[6] = {Wq + ow, Wk + ow, Wv + ow, Wkg + ow, Wvg + ow, Wo + ow};
        for (int i = 0; i < 6; i++)
            k_cvtw<<<dim3(HID / 32, HID / 32), 256>>>(Ws[i], pwt + (size_t)(l * 6 + i) * WSTRIDE, HID, HID);
        k_cvtw<<<dim3(HID / 32, FFNDIM / 32), 256>>>(W1 + ow1, pw1t + (size_t)l * FFNDIM * HID, HID, FFNDIM);
        k_cvtw<<<dim3(FFNDIM / 32, HID / 32), 256>>>(W2 + ow1, pw2t + (size_t)l * HID * FFNDIM, FFNDIM, HID);
    }

    k_embed<<<NTOK, 256>>>(ids, wemb, pemb, elns, elnb, px);

    const int CVT_H = NTOK * (HID / 4) / 256;     // 6144

    for (int l = 0; l < 2; l++) {
        size_t ow  = (size_t)l * HID * HID;
        size_t ob  = (size_t)l * HID;
        size_t ob1 = (size_t)l * FFNDIM;
        const __half* wl = pwt + (size_t)(l * 6) * WSTRIDE;

        // x -> fp16; 5 projections batched
        k_cvta<<<CVT_H, 256>>>(px, pab2);
        {
            TcB b5;
            b5.W[0] = wl + 0 * WSTRIDE; b5.b[0] = bq  + ob; b5.C[0] = pq;
            b5.W[1] = wl + 1 * WSTRIDE; b5.b[1] = bk  + ob; b5.C[1] = pk;
            b5.W[2] = wl + 2 * WSTRIDE; b5.b[2] = bv  + ob; b5.C[2] = pv;
            b5.W[3] = wl + 3 * WSTRIDE; b5.b[3] = bkg + ob; b5.C[3] = pkg;
            b5.W[4] = wl + 4 * WSTRIDE; b5.b[4] = bvg + ob; b5.C[4] = pvg;
            k_wmma<0><<<dim3(HID / 128, NTOK / 128, 5), 256, MM_SMEM>>>(pab2, b5, HID, HID);
        }
        k_qg0<<<dim3(3, BB), 256>>>(px, Wqg + ow, bqg + ob, pqg0);

        k_band<<<dim3(NC, HEADS, BB), 256>>>(pq, pk, pv, pkg, pvg, am, pattn);
        k_glob<<<BB * HEADS, 256>>>(pqg0, pkg, pvg, am, pattn);

        // attn @ Wo
        k_cvta<<<CVT_H, 256>>>(pattn, pab2);
        {
            TcB bo5; bo5.W[0] = wl + 5 * WSTRIDE; bo5.b[0] = bo + ob; bo5.C[0] = ptmp;
            k_wmma<0><<<dim3(HID / 128, NTOK / 128, 1), 256, MM_SMEM>>>(pab2, bo5, HID, HID);
        }
        k_addln<<<NTOK, 256>>>(ptmp, ln1s + ob, ln1b + ob, px);

        // FFN: W1 writes GELU'd fp16 directly into pab
        k_cvta<<<CVT_H, 256>>>(px, pab2);
        {
            TcB bw1; bw1.W[0] = pw1t + (size_t)l * FFNDIM * HID; bw1.b[0] = b1 + ob1;
            bw1.C[0] = (float*)pab;
            k_wmma<1><<<dim3(FFNDIM / 128, NTOK / 128, 1), 256, MM_SMEM>>>(pab2, bw1, FFNDIM, HID);
        }
        {
            TcB bw2; bw2.W[0] = pw2t + (size_t)l * HID * FFNDIM; bw2.b[0] = b2 + ob; bw2.C[0] = ptmp;
            k_wmma<0><<<dim3(HID / 128, NTOK / 128, 1), 256, MM_SMEM>>>(pab, bw2, HID, FFNDIM);
        }
        k_addln<<<NTOK, 256>>>(ptmp, ln2s + ob, ln2b + ob, px);
    }

    k_head<<<dim3((NLAB + 127) / 128, BB), 128>>>(px, hW, hb, out);
}